// round 1
// baseline (speedup 1.0000x reference)
#include <cuda_runtime.h>
#include <math.h>

// ---------------------------------------------------------------------------
// GraphNeuralNetwork forward:
//   h_sem    = relu(GO @ mlp_w1 + b1) @ mlp_w2 + b2                 [40000,512]
//   x        = relu(spmm(A, GO @ gc1_w) + gc1_b)                    [40000,1024]
//   h_struct = relu(spmm(A, x @ gc2_w) + gc2_b)                     [40000,512]
//   seq_out  = relu(SEQ @ se_w1 + se_b1) @ se_w2 + se_b2            [4096,1024]
//   pred     = sigmoid(seq_out @ concat(h_sem, h_struct)^T)         [4096,40000]
// Output = [h_sem | h_struct | pred] flattened.
// ---------------------------------------------------------------------------

#define N_GO    40000
#define GO_FEAT 512
#define SEQ_FEAT 1280
#define NHID0   1024
#define NHID1   512
#define N_EDGES 640000
#define SEQ_B   4096

// Scratch (static device globals -- no runtime allocation allowed)
__device__ float g_t1[(size_t)N_GO * NHID0];        // relu(GO@mlp_w1+b1)
__device__ float g_g1[(size_t)N_GO * NHID0];        // GO@gc1_w
__device__ float g_s1[(size_t)N_GO * NHID0];        // spmm1 accum / x
__device__ float g_g2[(size_t)N_GO * NHID1];        // x@gc2_w
__device__ float g_s2[(size_t)N_GO * NHID1];        // spmm2 accum
__device__ float g_u [(size_t)SEQ_B * NHID0];       // relu(SEQ@se_w1+b)
__device__ float g_so[(size_t)SEQ_B * NHID0];       // seq_out
__device__ float g_cat[(size_t)N_GO * (2 * NHID1)]; // concat(h_sem,h_struct)

static inline int cdiv(int a, int b) { return (a + b - 1) / b; }

// ---------------------------------------------------------------------------
// Tiled fp32 GEMM: C[M,N] = act(A[M,K] @ op(B) + bias)
//   TRANSB=false: B is [K,N] row-major.  TRANSB=true: B is [N,K] row-major.
//   act: 0=none, 1=relu, 2=sigmoid. bias may be null.
// Block tile 128x128, K-tile 16, 256 threads, 8x8 per-thread micro-tile.
// Requires K % 16 == 0 and N % 4 == 0 (true for all call sites here).
// ---------------------------------------------------------------------------
template <bool TRANSB>
__global__ void __launch_bounds__(256, 2) gemm128(
    const float* __restrict__ A, const float* __restrict__ B,
    const float* __restrict__ bias, float* __restrict__ C,
    int M, int N, int K, int act)
{
    __shared__ float As[16][132];
    __shared__ float Bs[16][132];

    const int tid = threadIdx.x;
    const int tx  = tid & 15;   // N direction (x8)
    const int ty  = tid >> 4;   // M direction (x8)
    const int m0  = blockIdx.y * 128;
    const int n0  = blockIdx.x * 128;

    float acc[8][8];
#pragma unroll
    for (int i = 0; i < 8; i++)
#pragma unroll
        for (int j = 0; j < 8; j++) acc[i][j] = 0.f;

    for (int k0 = 0; k0 < K; k0 += 16) {
        // ---- A tile: As[k][m] (transposed store) ----
#pragma unroll
        for (int i = 0; i < 2; i++) {
            int idx = tid + i * 256;          // 0..511
            int m   = idx >> 2;               // 0..127
            int k4  = (idx & 3) * 4;          // 0,4,8,12
            float4 a = make_float4(0.f, 0.f, 0.f, 0.f);
            if (m0 + m < M)
                a = *(const float4*)(A + (size_t)(m0 + m) * K + k0 + k4);
            As[k4 + 0][m] = a.x; As[k4 + 1][m] = a.y;
            As[k4 + 2][m] = a.z; As[k4 + 3][m] = a.w;
        }
        // ---- B tile: Bs[k][n] ----
        if (!TRANSB) {
#pragma unroll
            for (int i = 0; i < 2; i++) {
                int idx = tid + i * 256;
                int k   = idx >> 5;            // 0..15
                int n4  = (idx & 31) * 4;      // 0..124
                float4 b = make_float4(0.f, 0.f, 0.f, 0.f);
                if (n0 + n4 < N)
                    b = *(const float4*)(B + (size_t)(k0 + k) * N + n0 + n4);
                *(float4*)&Bs[k][n4] = b;
            }
        } else {
#pragma unroll
            for (int i = 0; i < 2; i++) {
                int idx = tid + i * 256;
                int n   = idx >> 2;            // 0..127
                int k4  = (idx & 3) * 4;
                float4 b = make_float4(0.f, 0.f, 0.f, 0.f);
                if (n0 + n < N)
                    b = *(const float4*)(B + (size_t)(n0 + n) * K + k0 + k4);
                Bs[k4 + 0][n] = b.x; Bs[k4 + 1][n] = b.y;
                Bs[k4 + 2][n] = b.z; Bs[k4 + 3][n] = b.w;
            }
        }
        __syncthreads();

#pragma unroll
        for (int k = 0; k < 16; k++) {
            float4 a0 = *(const float4*)&As[k][ty * 8];
            float4 a1 = *(const float4*)&As[k][ty * 8 + 4];
            float4 b0 = *(const float4*)&Bs[k][tx * 8];
            float4 b1 = *(const float4*)&Bs[k][tx * 8 + 4];
            float av[8] = {a0.x, a0.y, a0.z, a0.w, a1.x, a1.y, a1.z, a1.w};
            float bv[8] = {b0.x, b0.y, b0.z, b0.w, b1.x, b1.y, b1.z, b1.w};
#pragma unroll
            for (int i = 0; i < 8; i++)
#pragma unroll
                for (int j = 0; j < 8; j++)
                    acc[i][j] = fmaf(av[i], bv[j], acc[i][j]);
        }
        __syncthreads();
    }

    // ---- epilogue ----
    float bvals[8];
#pragma unroll
    for (int j = 0; j < 8; j++) {
        int cn = n0 + tx * 8 + j;
        bvals[j] = (bias != nullptr && cn < N) ? bias[cn] : 0.f;
    }
#pragma unroll
    for (int i = 0; i < 8; i++) {
        int cm = m0 + ty * 8 + i;
        if (cm >= M) continue;
#pragma unroll
        for (int j = 0; j < 8; j++) {
            int cn = n0 + tx * 8 + j;
            if (cn >= N) continue;
            float v = acc[i][j] + bvals[j];
            if (act == 1)      v = fmaxf(v, 0.f);
            else if (act == 2) v = 1.f / (1.f + __expf(-v));
            C[(size_t)cm * N + cn] = v;
        }
    }
}

// ---------------------------------------------------------------------------
// SpMM: out[row] += val * x[col]  (COO, atomics). One warp per edge per
// 128-column chunk; float4 atomicAdd (native vector RED on sm_90+).
// ---------------------------------------------------------------------------
__global__ void spmm_kernel(const int* __restrict__ erow, const int* __restrict__ ecol,
                            const float* __restrict__ eval, const float* __restrict__ x,
                            float* __restrict__ out, int nEdges, int d)
{
    int gw = (blockIdx.x * blockDim.x + threadIdx.x) >> 5;
    if (gw >= nEdges) return;
    int lane = threadIdx.x & 31;
    int r = erow[gw];
    int c = ecol[gw];
    float v = eval[gw];
    int off = blockIdx.y * 128 + lane * 4;
    float4 xv = *(const float4*)(x + (size_t)c * d + off);
    float4 add = make_float4(v * xv.x, v * xv.y, v * xv.z, v * xv.w);
    atomicAdd((float4*)(out + (size_t)r * d + off), add);
}

__global__ void zero_kernel(float4* __restrict__ p, long n4)
{
    long i = blockIdx.x * (long)blockDim.x + threadIdx.x;
    long stride = (long)gridDim.x * blockDim.x;
    for (; i < n4; i += stride) p[i] = make_float4(0.f, 0.f, 0.f, 0.f);
}

// out = relu(in + bias)  (vectorized, d % 4 == 0)
__global__ void bias_relu_kernel(const float* __restrict__ in, const float* __restrict__ b,
                                 float* __restrict__ out, long total4, int d4)
{
    long i = blockIdx.x * (long)blockDim.x + threadIdx.x;
    long stride = (long)gridDim.x * blockDim.x;
    for (; i < total4; i += stride) {
        int c4 = (int)(i % d4);
        float4 x  = ((const float4*)in)[i];
        float4 bb = ((const float4*)b)[c4];
        float4 y;
        y.x = fmaxf(x.x + bb.x, 0.f);
        y.y = fmaxf(x.y + bb.y, 0.f);
        y.z = fmaxf(x.z + bb.z, 0.f);
        y.w = fmaxf(x.w + bb.w, 0.f);
        ((float4*)out)[i] = y;
    }
}

// cat[n, 0:512] = a[n], cat[n, 512:1024] = b[n]
__global__ void concat_kernel(const float* __restrict__ a, const float* __restrict__ b,
                              float* __restrict__ cat)
{
    long i = blockIdx.x * (long)blockDim.x + threadIdx.x;  // over N_GO*256 float4
    long tot = (long)N_GO * 256;
    if (i >= tot) return;
    long row = i >> 8;
    int  c   = (int)(i & 255);
    float4 v = (c < 128) ? ((const float4*)a)[row * 128 + c]
                         : ((const float4*)b)[row * 128 + (c - 128)];
    ((float4*)cat)[i] = v;
}

// ---------------------------------------------------------------------------
extern "C" void kernel_launch(void* const* d_in, const int* in_sizes, int n_in,
                              void* d_out, int out_size)
{
    const float* seq    = (const float*)d_in[0];   // [4096,1280]
    const float* go     = (const float*)d_in[1];   // [40000,512]
    const int*   erow   = (const int*)  d_in[2];   // [640000]
    const int*   ecol   = (const int*)  d_in[3];
    const float* eval_  = (const float*)d_in[4];
    const float* mlp_w1 = (const float*)d_in[5];   // [512,1024]
    const float* mlp_b1 = (const float*)d_in[6];
    const float* mlp_w2 = (const float*)d_in[7];   // [1024,512]
    const float* mlp_b2 = (const float*)d_in[8];
    const float* gc1_w  = (const float*)d_in[9];   // [512,1024]
    const float* gc1_b  = (const float*)d_in[10];
    const float* gc2_w  = (const float*)d_in[11];  // [1024,512]
    const float* gc2_b  = (const float*)d_in[12];
    const float* se_w1  = (const float*)d_in[13];  // [1280,1024]
    const float* se_b1  = (const float*)d_in[14];
    const float* se_w2  = (const float*)d_in[15];  // [1024,1024]
    const float* se_b2  = (const float*)d_in[16];

    float* out  = (float*)d_out;
    float* hsem = out;                                        // [40000,512]
    float* hstr = out + (size_t)N_GO * NHID1;                 // [40000,512]
    float* pred = out + (size_t)2 * N_GO * NHID1;             // [4096,40000]

    float *t1, *g1, *s1, *g2, *s2, *u, *so, *cat;
    cudaGetSymbolAddress((void**)&t1,  g_t1);
    cudaGetSymbolAddress((void**)&g1,  g_g1);
    cudaGetSymbolAddress((void**)&s1,  g_s1);
    cudaGetSymbolAddress((void**)&g2,  g_g2);
    cudaGetSymbolAddress((void**)&s2,  g_s2);
    cudaGetSymbolAddress((void**)&u,   g_u);
    cudaGetSymbolAddress((void**)&so,  g_so);
    cudaGetSymbolAddress((void**)&cat, g_cat);

    const int T = 256;

    // zero spmm accumulators
    zero_kernel<<<4096, T>>>((float4*)s1, (long)N_GO * NHID0 / 4);
    zero_kernel<<<4096, T>>>((float4*)s2, (long)N_GO * NHID1 / 4);

    // semantic branch
    gemm128<false><<<dim3(NHID0 / 128, cdiv(N_GO, 128)), T>>>(
        go, mlp_w1, mlp_b1, t1, N_GO, NHID0, GO_FEAT, 1);
    gemm128<false><<<dim3(NHID1 / 128, cdiv(N_GO, 128)), T>>>(
        t1, mlp_w2, mlp_b2, hsem, N_GO, NHID1, NHID0, 0);

    // structure branch
    gemm128<false><<<dim3(NHID0 / 128, cdiv(N_GO, 128)), T>>>(
        go, gc1_w, nullptr, g1, N_GO, NHID0, GO_FEAT, 0);
    spmm_kernel<<<dim3(N_EDGES * 32 / T, NHID0 / 128), T>>>(
        erow, ecol, eval_, g1, s1, N_EDGES, NHID0);
    bias_relu_kernel<<<4096, T>>>(s1, gc1_b, s1, (long)N_GO * NHID0 / 4, NHID0 / 4);
    gemm128<false><<<dim3(NHID1 / 128, cdiv(N_GO, 128)), T>>>(
        s1, gc2_w, nullptr, g2, N_GO, NHID1, NHID0, 0);
    spmm_kernel<<<dim3(N_EDGES * 32 / T, NHID1 / 128), T>>>(
        erow, ecol, eval_, g2, s2, N_EDGES, NHID1);
    bias_relu_kernel<<<4096, T>>>(s2, gc2_b, hstr, (long)N_GO * NHID1 / 4, NHID1 / 4);

    // sequence encoder
    gemm128<false><<<dim3(NHID0 / 128, SEQ_B / 128), T>>>(
        seq, se_w1, se_b1, u, SEQ_B, NHID0, SEQ_FEAT, 1);
    gemm128<false><<<dim3(NHID0 / 128, SEQ_B / 128), T>>>(
        u, se_w2, se_b2, so, SEQ_B, NHID0, NHID0, 0);

    // concat GO features, prediction GEMM (NT) with sigmoid epilogue
    concat_kernel<<<cdiv(N_GO * 256, T), T>>>(hsem, hstr, cat);
    gemm128<true><<<dim3(cdiv(N_GO, 128), SEQ_B / 128), T>>>(
        so, cat, nullptr, pred, SEQ_B, N_GO, 2 * NHID1, 2);
}

// round 3
// speedup vs baseline: 2.1053x; 2.1053x over previous
#include <cuda_runtime.h>
#include <cstdint>
#include <math.h>

// ---------------------------------------------------------------------------
// GraphNeuralNetwork forward, GEMMs on mma.sync tf32 tensor cores (sm_80+
// PTX path -- valid under the harness's compute_103 lowering).
//   h_sem    = relu(GO @ mlp_w1 + b1) @ mlp_w2 + b2                 [40000,512]
//   x        = relu(spmm(A, GO @ gc1_w) + gc1_b)                    [40000,1024]
//   h_struct = relu(spmm(A, x @ gc2_w) + gc2_b)                     [40000,512]
//   seq_out  = relu(SEQ @ se_w1 + se_b1) @ se_w2 + se_b2            [4096,1024]
//   pred     = sigmoid(seq_out @ concat(h_sem, h_struct)^T)         [4096,40000]
// ---------------------------------------------------------------------------

#define N_GO    40000
#define GO_FEAT 512
#define SEQ_FEAT 1280
#define NHID0   1024
#define NHID1   512
#define N_EDGES 640000
#define SEQ_B   4096

// ---------------- scratch (no runtime allocation allowed) ------------------
__device__ float g_t1[(size_t)N_GO * NHID0];
__device__ float g_g1[(size_t)N_GO * NHID0];
__device__ float g_s1[(size_t)N_GO * NHID0];
__device__ float g_g2[(size_t)N_GO * NHID1];
__device__ float g_s2[(size_t)N_GO * NHID1];
__device__ float g_u [(size_t)SEQ_B * NHID0];
__device__ float g_so[(size_t)SEQ_B * NHID0];
__device__ float g_cat[(size_t)N_GO * 1024];
__device__ float g_wt[4456448];   // transposed weights arena

static inline int cdiv(int a, int b) { return (a + b - 1) / b; }

// ---------------------------------------------------------------------------
// tf32 conversion + mma.sync helpers (plain sm_80+ PTX, no arch-a features)
// ---------------------------------------------------------------------------
__device__ __forceinline__ uint32_t f2tf32(float x) {
    uint32_t r;
    asm("cvt.rna.tf32.f32 %0, %1;" : "=r"(r) : "f"(x));
    return r;
}

__device__ __forceinline__ void mma_tf32(float c[4], const uint32_t a[4],
                                         const uint32_t b[2]) {
    asm volatile(
        "mma.sync.aligned.m16n8k8.row.col.f32.tf32.tf32.f32 "
        "{%0,%1,%2,%3}, {%4,%5,%6,%7}, {%8,%9}, {%0,%1,%2,%3};"
        : "+f"(c[0]), "+f"(c[1]), "+f"(c[2]), "+f"(c[3])
        : "r"(a[0]), "r"(a[1]), "r"(a[2]), "r"(a[3]), "r"(b[0]), "r"(b[1]));
}

// ---------------------------------------------------------------------------
// Tensor-core GEMM: C[M,N] = act(A[M,K] @ B[N,K]^T + bias)
// Both operands row-major, K contiguous (NT). CTA tile 128x128, K-tile 32,
// 8 warps (2x4), warp tile 64x32, double-buffered SMEM (pitch 36 floats ->
// conflict-free LDS fragment loads). act: 0=none 1=relu 2=sigmoid.
// Optional dual output C2 with row stride ldc2 (floats).
// Requirements: K % 32 == 0, N even.
// ---------------------------------------------------------------------------
#define PITCH 36
#define TILE_WORDS (128 * PITCH)              // 4608 floats per operand tile
#define STAGE_WORDS (2 * TILE_WORDS)          // A + B
#define GEMM_SMEM_BYTES (2 * STAGE_WORDS * 4) // 73728 bytes

__global__ void __launch_bounds__(256, 1) gemm_mma(
    const float* __restrict__ A, const float* __restrict__ B,
    const float* __restrict__ bias, float* __restrict__ C,
    float* __restrict__ C2, int ldc2,
    int M, int N, int K, int act)
{
    extern __shared__ float sm[];

    const int tid  = threadIdx.x;
    const int wid  = tid >> 5;
    const int lane = tid & 31;
    const int g    = lane >> 2;      // group id 0..7
    const int tig  = lane & 3;       // thread-in-group 0..3
    const int wm   = wid >> 2;       // warp M index 0..1
    const int wn   = wid & 3;        // warp N index 0..3
    const int n0   = blockIdx.x * 128;
    const int m0   = blockIdx.y * 128;

    // staging registers for the next K-tile
    float4 ra[4], rb[4];
    // per-thread copy coordinates: idx = tid + it*256 in [0,1024)
    //   r = idx>>3 (row 0..127), k4 = (idx&7)*4 (k offset 0..28)

    float acc[4][4][4];
#pragma unroll
    for (int i = 0; i < 4; i++)
#pragma unroll
        for (int j = 0; j < 4; j++)
#pragma unroll
            for (int t = 0; t < 4; t++) acc[i][j][t] = 0.f;

    const int nkt = K >> 5;

    // ---- global load of K-tile kt into registers ----
    auto stage_g = [&](int kt) {
        const int k0 = kt << 5;
#pragma unroll
        for (int it = 0; it < 4; it++) {
            int idx = tid + it * 256;
            int r   = idx >> 3;
            int k4  = (idx & 7) << 2;
            int m = m0 + r, n = n0 + r;
            ra[it] = make_float4(0.f, 0.f, 0.f, 0.f);
            rb[it] = make_float4(0.f, 0.f, 0.f, 0.f);
            if (m < M) ra[it] = *(const float4*)(A + (size_t)m * K + k0 + k4);
            if (n < N) rb[it] = *(const float4*)(B + (size_t)n * K + k0 + k4);
        }
    };

    // ---- store staged registers (tf32-converted) into smem buffer s ----
    auto stage_s = [&](int s) {
        float* as = sm + s * STAGE_WORDS;
        float* bs = as + TILE_WORDS;
#pragma unroll
        for (int it = 0; it < 4; it++) {
            int idx = tid + it * 256;
            int r   = idx >> 3;
            int k4  = (idx & 7) << 2;
            float4 v = ra[it];
            float4 w = rb[it];
            float4 vc = make_float4(__uint_as_float(f2tf32(v.x)),
                                    __uint_as_float(f2tf32(v.y)),
                                    __uint_as_float(f2tf32(v.z)),
                                    __uint_as_float(f2tf32(v.w)));
            float4 wc = make_float4(__uint_as_float(f2tf32(w.x)),
                                    __uint_as_float(f2tf32(w.y)),
                                    __uint_as_float(f2tf32(w.z)),
                                    __uint_as_float(f2tf32(w.w)));
            *(float4*)(as + r * PITCH + k4) = vc;
            *(float4*)(bs + r * PITCH + k4) = wc;
        }
    };

    // ---- MMA over one K-tile in smem buffer s ----
    auto compute = [&](int s) {
        const float* as = sm + s * STAGE_WORDS;
        const float* bs = as + TILE_WORDS;
        const int arow = (wm * 64 + g) * PITCH;
        const int brow = (wn * 32 + g) * PITCH;
#pragma unroll
        for (int kk = 0; kk < 4; kk++) {
            const int kc = kk * 8 + tig;
            uint32_t af[4][4];
#pragma unroll
            for (int i = 0; i < 4; i++) {
                int base = arow + i * 16 * PITCH;
                af[i][0] = __float_as_uint(as[base + kc]);
                af[i][1] = __float_as_uint(as[base + 8 * PITCH + kc]);
                af[i][2] = __float_as_uint(as[base + kc + 4]);
                af[i][3] = __float_as_uint(as[base + 8 * PITCH + kc + 4]);
            }
            uint32_t bf[4][2];
#pragma unroll
            for (int j = 0; j < 4; j++) {
                int base = brow + j * 8 * PITCH;
                bf[j][0] = __float_as_uint(bs[base + kc]);
                bf[j][1] = __float_as_uint(bs[base + kc + 4]);
            }
#pragma unroll
            for (int i = 0; i < 4; i++)
#pragma unroll
                for (int j = 0; j < 4; j++)
                    mma_tf32(acc[i][j], af[i], bf[j]);
        }
    };

    // ---- pipelined main loop ----
    stage_g(0);
    stage_s(0);
    __syncthreads();
    for (int kt = 0; kt < nkt; kt++) {
        const int cur = kt & 1;
        if (kt + 1 < nkt) stage_g(kt + 1);
        compute(cur);
        if (kt + 1 < nkt) {
            stage_s(cur ^ 1);
            __syncthreads();
        }
    }

    // ---- epilogue ----
#pragma unroll
    for (int i = 0; i < 4; i++) {
        const int r0 = m0 + wm * 64 + 16 * i + g;
#pragma unroll
        for (int j = 0; j < 4; j++) {
            const int cn = n0 + wn * 32 + 8 * j + 2 * tig;
            if (cn >= N) continue;
            float b0 = 0.f, b1 = 0.f;
            if (bias != nullptr) { b0 = bias[cn]; b1 = bias[cn + 1]; }
#pragma unroll
            for (int h = 0; h < 2; h++) {
                const int r = r0 + h * 8;
                if (r >= M) continue;
                float x0 = acc[i][j][2 * h]     + b0;
                float x1 = acc[i][j][2 * h + 1] + b1;
                if (act == 1) { x0 = fmaxf(x0, 0.f); x1 = fmaxf(x1, 0.f); }
                else if (act == 2) {
                    x0 = 1.f / (1.f + __expf(-x0));
                    x1 = 1.f / (1.f + __expf(-x1));
                }
                float2 o = make_float2(x0, x1);
                *(float2*)(C + (size_t)r * N + cn) = o;
                if (C2) *(float2*)(C2 + (size_t)r * ldc2 + cn) = o;
            }
        }
    }
}

// ---------------------------------------------------------------------------
// transpose: out[c][r] = in[r][c]
// ---------------------------------------------------------------------------
__global__ void transpose_k(const float* __restrict__ in, float* __restrict__ out,
                            int R, int C)
{
    __shared__ float t[32][33];
    int bx = blockIdx.x * 32, by = blockIdx.y * 32;
    int x = bx + threadIdx.x;
    int y = by + threadIdx.y;
#pragma unroll
    for (int j = 0; j < 32; j += 8)
        if (y + j < R && x < C) t[threadIdx.y + j][threadIdx.x] = in[(size_t)(y + j) * C + x];
    __syncthreads();
    x = by + threadIdx.x;
    y = bx + threadIdx.y;
#pragma unroll
    for (int j = 0; j < 32; j += 8)
        if (y + j < C && x < R) out[(size_t)(y + j) * R + x] = t[threadIdx.x][threadIdx.y + j];
}

// ---------------------------------------------------------------------------
// SpMM (COO, float4 atomics): out[row] += val * x[col]
// ---------------------------------------------------------------------------
__global__ void spmm_kernel(const int* __restrict__ erow, const int* __restrict__ ecol,
                            const float* __restrict__ eval, const float* __restrict__ x,
                            float* __restrict__ out, int nEdges, int d)
{
    int gw = (blockIdx.x * blockDim.x + threadIdx.x) >> 5;
    if (gw >= nEdges) return;
    int lane = threadIdx.x & 31;
    int r = erow[gw];
    int c = ecol[gw];
    float v = eval[gw];
    int off = blockIdx.y * 128 + lane * 4;
    float4 xv = *(const float4*)(x + (size_t)c * d + off);
    float4 add = make_float4(v * xv.x, v * xv.y, v * xv.z, v * xv.w);
    atomicAdd((float4*)(out + (size_t)r * d + off), add);
}

__global__ void zero_kernel(float4* __restrict__ p, long n4)
{
    long i = blockIdx.x * (long)blockDim.x + threadIdx.x;
    long stride = (long)gridDim.x * blockDim.x;
    for (; i < n4; i += stride) p[i] = make_float4(0.f, 0.f, 0.f, 0.f);
}

// out = relu(in + bias); optional second copy at out2 (float4 row stride ld2_4)
__global__ void bias_relu_k(const float* __restrict__ in, const float* __restrict__ b,
                            float* __restrict__ out, float* __restrict__ out2, int ld2_4,
                            long total4, int d4)
{
    long i = blockIdx.x * (long)blockDim.x + threadIdx.x;
    long stride = (long)gridDim.x * blockDim.x;
    for (; i < total4; i += stride) {
        int  c4  = (int)(i % d4);
        long row = i / d4;
        float4 x  = ((const float4*)in)[i];
        float4 bb = ((const float4*)b)[c4];
        float4 y;
        y.x = fmaxf(x.x + bb.x, 0.f);
        y.y = fmaxf(x.y + bb.y, 0.f);
        y.z = fmaxf(x.z + bb.z, 0.f);
        y.w = fmaxf(x.w + bb.w, 0.f);
        ((float4*)out)[i] = y;
        if (out2) ((float4*)out2)[row * ld2_4 + c4] = y;
    }
}

// ---------------------------------------------------------------------------
extern "C" void kernel_launch(void* const* d_in, const int* in_sizes, int n_in,
                              void* d_out, int out_size)
{
    const float* seq    = (const float*)d_in[0];
    const float* go     = (const float*)d_in[1];
    const int*   erow   = (const int*)  d_in[2];
    const int*   ecol   = (const int*)  d_in[3];
    const float* eval_  = (const float*)d_in[4];
    const float* mlp_w1 = (const float*)d_in[5];
    const float* mlp_b1 = (const float*)d_in[6];
    const float* mlp_w2 = (const float*)d_in[7];
    const float* mlp_b2 = (const float*)d_in[8];
    const float* gc1_w  = (const float*)d_in[9];
    const float* gc1_b  = (const float*)d_in[10];
    const float* gc2_w  = (const float*)d_in[11];
    const float* gc2_b  = (const float*)d_in[12];
    const float* se_w1  = (const float*)d_in[13];
    const float* se_b1  = (const float*)d_in[14];
    const float* se_w2  = (const float*)d_in[15];
    const float* se_b2  = (const float*)d_in[16];

    float* out  = (float*)d_out;
    float* hsem = out;
    float* hstr = out + (size_t)N_GO * NHID1;
    float* pred = out + (size_t)2 * N_GO * NHID1;

    float *t1, *g1, *s1, *g2, *s2, *u, *so, *cat, *wt;
    cudaGetSymbolAddress((void**)&t1,  g_t1);
    cudaGetSymbolAddress((void**)&g1,  g_g1);
    cudaGetSymbolAddress((void**)&s1,  g_s1);
    cudaGetSymbolAddress((void**)&g2,  g_g2);
    cudaGetSymbolAddress((void**)&s2,  g_s2);
    cudaGetSymbolAddress((void**)&u,   g_u);
    cudaGetSymbolAddress((void**)&so,  g_so);
    cudaGetSymbolAddress((void**)&cat, g_cat);
    cudaGetSymbolAddress((void**)&wt,  g_wt);

    float* wt_mlp1 = wt + 0;        // [1024,512]
    float* wt_mlp2 = wt + 524288;   // [512,1024]
    float* wt_gc1  = wt + 1048576;  // [1024,512]
    float* wt_gc2  = wt + 1572864;  // [512,1024]
    float* wt_se1  = wt + 2097152;  // [1024,1280]
    float* wt_se2  = wt + 3407872;  // [1024,1024]

    cudaFuncSetAttribute(gemm_mma, cudaFuncAttributeMaxDynamicSharedMemorySize,
                         GEMM_SMEM_BYTES);

    const int T = 256;
    dim3 tb(32, 8);

    // weight transposes (to [N,K] K-major)
    transpose_k<<<dim3(1024 / 32, 512 / 32),  tb>>>(mlp_w1, wt_mlp1, 512, 1024);
    transpose_k<<<dim3(512 / 32,  1024 / 32), tb>>>(mlp_w2, wt_mlp2, 1024, 512);
    transpose_k<<<dim3(1024 / 32, 512 / 32),  tb>>>(gc1_w,  wt_gc1,  512, 1024);
    transpose_k<<<dim3(512 / 32,  1024 / 32), tb>>>(gc2_w,  wt_gc2,  1024, 512);
    transpose_k<<<dim3(1024 / 32, 1280 / 32), tb>>>(se_w1,  wt_se1,  1280, 1024);
    transpose_k<<<dim3(1024 / 32, 1024 / 32), tb>>>(se_w2,  wt_se2,  1024, 1024);

    // zero spmm accumulators
    zero_kernel<<<4096, T>>>((float4*)s1, (long)N_GO * NHID0 / 4);
    zero_kernel<<<4096, T>>>((float4*)s2, (long)N_GO * NHID1 / 4);

    const int MT_GO  = cdiv(N_GO, 128);   // 313
    const int MT_SEQ = SEQ_B / 128;       // 32

    // semantic branch
    gemm_mma<<<dim3(NHID0 / 128, MT_GO), T, GEMM_SMEM_BYTES>>>(
        go, wt_mlp1, mlp_b1, t1, nullptr, 0, N_GO, NHID0, GO_FEAT, 1);
    gemm_mma<<<dim3(NHID1 / 128, MT_GO), T, GEMM_SMEM_BYTES>>>(
        t1, wt_mlp2, mlp_b2, hsem, cat, 1024, N_GO, NHID1, NHID0, 0);

    // structure branch
    gemm_mma<<<dim3(NHID0 / 128, MT_GO), T, GEMM_SMEM_BYTES>>>(
        go, wt_gc1, nullptr, g1, nullptr, 0, N_GO, NHID0, GO_FEAT, 0);
    spmm_kernel<<<dim3(N_EDGES * 32 / T, NHID0 / 128), T>>>(
        erow, ecol, eval_, g1, s1, N_EDGES, NHID0);
    bias_relu_k<<<4096, T>>>(s1, gc1_b, s1, nullptr, 0,
                             (long)N_GO * NHID0 / 4, NHID0 / 4);
    gemm_mma<<<dim3(NHID1 / 128, MT_GO), T, GEMM_SMEM_BYTES>>>(
        s1, wt_gc2, nullptr, g2, nullptr, 0, N_GO, NHID1, NHID0, 0);
    spmm_kernel<<<dim3(N_EDGES * 32 / T, NHID1 / 128), T>>>(
        erow, ecol, eval_, g2, s2, N_EDGES, NHID1);
    bias_relu_k<<<4096, T>>>(s2, gc2_b, hstr, cat + 512, 256,
                             (long)N_GO * NHID1 / 4, NHID1 / 4);

    // sequence encoder
    gemm_mma<<<dim3(NHID0 / 128, MT_SEQ), T, GEMM_SMEM_BYTES>>>(
        seq, wt_se1, se_b1, u, nullptr, 0, SEQ_B, NHID0, SEQ_FEAT, 1);
    gemm_mma<<<dim3(NHID0 / 128, MT_SEQ), T, GEMM_SMEM_BYTES>>>(
        u, wt_se2, se_b2, so, nullptr, 0, SEQ_B, NHID0, NHID0, 0);

    // prediction: sigmoid(so[4096,1024] @ cat[40000,1024]^T)
    gemm_mma<<<dim3(MT_GO, MT_SEQ), T, GEMM_SMEM_BYTES>>>(
        so, cat, nullptr, pred, nullptr, 0, SEQ_B, N_GO, NHID0, 2);
}

// round 4
// speedup vs baseline: 2.8515x; 1.3545x over previous
#include <cuda_runtime.h>
#include <cstdint>
#include <math.h>

// ---------------------------------------------------------------------------
// GraphNeuralNetwork forward, GEMMs on mma.sync tf32 tensor cores with
// cp.async 3-stage pipelines (sm_80+ PTX path, valid under compute_103).
// All GEMM inputs are pre-rounded to tf32 so the GEMM copies bytes directly.
// ---------------------------------------------------------------------------

#define N_GO    40000
#define GO_FEAT 512
#define SEQ_FEAT 1280
#define NHID0   1024
#define NHID1   512
#define N_EDGES 640000
#define SEQ_B   4096

// ---------------- scratch (no runtime allocation allowed) ------------------
__device__ float g_t1[(size_t)N_GO * NHID0];
__device__ float g_g1[(size_t)N_GO * NHID0];
__device__ float g_s1[(size_t)N_GO * NHID0];
__device__ float g_g2[(size_t)N_GO * NHID1];
__device__ float g_s2[(size_t)N_GO * NHID1];
__device__ float g_u [(size_t)SEQ_B * NHID0];
__device__ float g_so[(size_t)SEQ_B * NHID0];
__device__ float g_cat[(size_t)N_GO * 1024];
__device__ float g_goc[(size_t)N_GO * GO_FEAT];    // tf32-rounded go
__device__ float g_seqc[(size_t)SEQ_B * SEQ_FEAT]; // tf32-rounded seq
__device__ float g_wt[4456448];                    // transposed+rounded weights

static inline int cdiv(int a, int b) { return (a + b - 1) / b; }

// ---------------------------------------------------------------------------
__device__ __forceinline__ float f2tf32r(float x) {
    uint32_t r;
    asm("cvt.rna.tf32.f32 %0, %1;" : "=r"(r) : "f"(x));
    return __uint_as_float(r);
}

__device__ __forceinline__ void mma_tf32(float c[4], const uint32_t a[4],
                                         const uint32_t b[2]) {
    asm volatile(
        "mma.sync.aligned.m16n8k8.row.col.f32.tf32.tf32.f32 "
        "{%0,%1,%2,%3}, {%4,%5,%6,%7}, {%8,%9}, {%0,%1,%2,%3};"
        : "+f"(c[0]), "+f"(c[1]), "+f"(c[2]), "+f"(c[3])
        : "r"(a[0]), "r"(a[1]), "r"(a[2]), "r"(a[3]), "r"(b[0]), "r"(b[1]));
}

__device__ __forceinline__ uint32_t smem_u32(const void* p) {
    uint32_t a;
    asm("{ .reg .u64 t; cvta.to.shared.u64 t, %1; cvt.u32.u64 %0, t; }"
        : "=r"(a) : "l"(p));
    return a;
}

__device__ __forceinline__ void cp_async16(uint32_t dst, const void* src, bool valid) {
    int sz = valid ? 16 : 0;
    asm volatile("cp.async.cg.shared.global [%0], [%1], 16, %2;"
                 :: "r"(dst), "l"(src), "r"(sz) : "memory");
}
#define CP_COMMIT() asm volatile("cp.async.commit_group;" ::: "memory")
#define CP_WAIT1()  asm volatile("cp.async.wait_group 1;" ::: "memory")

// ---------------------------------------------------------------------------
// GEMM: C[M,N] = act(A[M,K] @ B[N,K]^T + bias). Both operands row-major,
// K contiguous, values already tf32-rounded. CTA tile 128x128, K-tile 32,
// 8 warps (2x4), warp tile 64x32, 3-stage cp.async pipeline, pitch-36 SMEM.
// act: 0=none 1=relu 2=sigmoid. roundC/roundC2: tf32-round that output.
// Requirements: K % 32 == 0, N even, A/B rows 16B-aligned (K % 4 == 0).
// ---------------------------------------------------------------------------
#define PITCH 36
#define TILE_WORDS (128 * PITCH)
#define STAGE_WORDS (2 * TILE_WORDS)
#define NSTAGE 3
#define GEMM_SMEM_BYTES (NSTAGE * STAGE_WORDS * 4)   // 110592

__global__ void __launch_bounds__(256, 2) gemm_mma(
    const float* __restrict__ A, const float* __restrict__ B,
    const float* __restrict__ bias, float* __restrict__ C,
    float* __restrict__ C2, int ldc2,
    int M, int N, int K, int act, int roundC, int roundC2)
{
    extern __shared__ float sm[];
    const uint32_t smem_base = smem_u32(sm);

    const int tid  = threadIdx.x;
    const int wid  = tid >> 5;
    const int lane = tid & 31;
    const int g    = lane >> 2;
    const int tig  = lane & 3;
    const int wm   = wid >> 2;
    const int wn   = wid & 3;
    const int n0   = blockIdx.x * 128;
    const int m0   = blockIdx.y * 128;

    // per-thread copy coords (fixed): idx = tid + it*256; r=idx>>3; k4=(idx&7)*4
    const int nkt = K >> 5;

    auto issue = [&](int kt) {
        if (kt < nkt) {
            const int k0 = kt << 5;
            const uint32_t sbase = smem_base + (uint32_t)(kt % NSTAGE) * (STAGE_WORDS * 4);
#pragma unroll
            for (int it = 0; it < 4; it++) {
                int idx = tid + it * 256;
                int r   = idx >> 3;
                int k4  = (idx & 7) << 2;
                uint32_t da = sbase + (uint32_t)(r * PITCH + k4) * 4;
                cp_async16(da, A + (size_t)(m0 + r) * K + k0 + k4, (m0 + r) < M);
                cp_async16(da + TILE_WORDS * 4, B + (size_t)(n0 + r) * K + k0 + k4,
                           (n0 + r) < N);
            }
        }
        CP_COMMIT();
    };

    float acc[4][4][4];
#pragma unroll
    for (int i = 0; i < 4; i++)
#pragma unroll
        for (int j = 0; j < 4; j++)
#pragma unroll
            for (int t = 0; t < 4; t++) acc[i][j][t] = 0.f;

    issue(0);
    issue(1);

    const int arow = (wm * 64 + g) * PITCH;
    const int brow = (wn * 32 + g) * PITCH;

    for (int kt = 0; kt < nkt; kt++) {
        CP_WAIT1();
        __syncthreads();
        issue(kt + 2);

        const float* as = sm + (kt % NSTAGE) * STAGE_WORDS;
        const float* bs = as + TILE_WORDS;
#pragma unroll
        for (int kk = 0; kk < 4; kk++) {
            const int kc = kk * 8 + tig;
            uint32_t af[4][4];
#pragma unroll
            for (int i = 0; i < 4; i++) {
                int base = arow + i * 16 * PITCH;
                af[i][0] = __float_as_uint(as[base + kc]);
                af[i][1] = __float_as_uint(as[base + 8 * PITCH + kc]);
                af[i][2] = __float_as_uint(as[base + kc + 4]);
                af[i][3] = __float_as_uint(as[base + 8 * PITCH + kc + 4]);
            }
            uint32_t bf[4][2];
#pragma unroll
            for (int j = 0; j < 4; j++) {
                int base = brow + j * 8 * PITCH;
                bf[j][0] = __float_as_uint(bs[base + kc]);
                bf[j][1] = __float_as_uint(bs[base + kc + 4]);
            }
#pragma unroll
            for (int i = 0; i < 4; i++)
#pragma unroll
                for (int j = 0; j < 4; j++)
                    mma_tf32(acc[i][j], af[i], bf[j]);
        }
        __syncthreads();
    }

    // ---- epilogue ----
#pragma unroll
    for (int i = 0; i < 4; i++) {
        const int r0 = m0 + wm * 64 + 16 * i + g;
#pragma unroll
        for (int j = 0; j < 4; j++) {
            const int cn = n0 + wn * 32 + 8 * j + 2 * tig;
            if (cn >= N) continue;
            float b0 = 0.f, b1 = 0.f;
            if (bias != nullptr) { b0 = bias[cn]; b1 = bias[cn + 1]; }
#pragma unroll
            for (int h = 0; h < 2; h++) {
                const int r = r0 + h * 8;
                if (r >= M) continue;
                float x0 = acc[i][j][2 * h]     + b0;
                float x1 = acc[i][j][2 * h + 1] + b1;
                if (act == 1) { x0 = fmaxf(x0, 0.f); x1 = fmaxf(x1, 0.f); }
                else if (act == 2) {
                    x0 = 1.f / (1.f + __expf(-x0));
                    x1 = 1.f / (1.f + __expf(-x1));
                }
                float c0 = roundC ? f2tf32r(x0) : x0;
                float c1 = roundC ? f2tf32r(x1) : x1;
                *(float2*)(C + (size_t)r * N + cn) = make_float2(c0, c1);
                if (C2) {
                    float d0 = roundC2 ? f2tf32r(x0) : x0;
                    float d1 = roundC2 ? f2tf32r(x1) : x1;
                    *(float2*)(C2 + (size_t)r * ldc2 + cn) = make_float2(d0, d1);
                }
            }
        }
    }
}

// ---------------------------------------------------------------------------
// transpose + tf32-round: out[c][r] = round(in[r][c])
// ---------------------------------------------------------------------------
__global__ void transpose_k(const float* __restrict__ in, float* __restrict__ out,
                            int R, int C)
{
    __shared__ float t[32][33];
    int bx = blockIdx.x * 32, by = blockIdx.y * 32;
    int x = bx + threadIdx.x;
    int y = by + threadIdx.y;
#pragma unroll
    for (int j = 0; j < 32; j += 8)
        if (y + j < R && x < C) t[threadIdx.y + j][threadIdx.x] = in[(size_t)(y + j) * C + x];
    __syncthreads();
    x = by + threadIdx.x;
    y = bx + threadIdx.y;
#pragma unroll
    for (int j = 0; j < 32; j += 8)
        if (y + j < C && x < R)
            out[(size_t)(y + j) * R + x] = f2tf32r(t[threadIdx.x][threadIdx.y + j]);
}

// elementwise tf32 rounding
__global__ void round_k(const float* __restrict__ in, float* __restrict__ out, long n4)
{
    long i = blockIdx.x * (long)blockDim.x + threadIdx.x;
    long stride = (long)gridDim.x * blockDim.x;
    for (; i < n4; i += stride) {
        float4 v = ((const float4*)in)[i];
        v.x = f2tf32r(v.x); v.y = f2tf32r(v.y);
        v.z = f2tf32r(v.z); v.w = f2tf32r(v.w);
        ((float4*)out)[i] = v;
    }
}

// ---------------------------------------------------------------------------
// SpMM (COO, float4 atomics): out[row] += val * x[col]
// ---------------------------------------------------------------------------
__global__ void spmm_kernel(const int* __restrict__ erow, const int* __restrict__ ecol,
                            const float* __restrict__ eval, const float* __restrict__ x,
                            float* __restrict__ out, int nEdges, int d)
{
    int gw = (blockIdx.x * blockDim.x + threadIdx.x) >> 5;
    if (gw >= nEdges) return;
    int lane = threadIdx.x & 31;
    int r = erow[gw];
    int c = ecol[gw];
    float v = eval[gw];
    int off = blockIdx.y * 128 + lane * 4;
    float4 xv = *(const float4*)(x + (size_t)c * d + off);
    float4 add = make_float4(v * xv.x, v * xv.y, v * xv.z, v * xv.w);
    atomicAdd((float4*)(out + (size_t)r * d + off), add);
}

__global__ void zero_kernel(float4* __restrict__ p, long n4)
{
    long i = blockIdx.x * (long)blockDim.x + threadIdx.x;
    long stride = (long)gridDim.x * blockDim.x;
    for (; i < n4; i += stride) p[i] = make_float4(0.f, 0.f, 0.f, 0.f);
}

// out = relu(in + bias) [optionally tf32-rounded]; optional second copy out2.
__global__ void bias_relu_k(const float* __restrict__ in, const float* __restrict__ b,
                            float* __restrict__ out, int rnd,
                            float* __restrict__ out2, int ld2_4, int rnd2,
                            long total4, int d4)
{
    long i = blockIdx.x * (long)blockDim.x + threadIdx.x;
    long stride = (long)gridDim.x * blockDim.x;
    for (; i < total4; i += stride) {
        int  c4  = (int)(i % d4);
        long row = i / d4;
        float4 x  = ((const float4*)in)[i];
        float4 bb = ((const float4*)b)[c4];
        float4 y;
        y.x = fmaxf(x.x + bb.x, 0.f);
        y.y = fmaxf(x.y + bb.y, 0.f);
        y.z = fmaxf(x.z + bb.z, 0.f);
        y.w = fmaxf(x.w + bb.w, 0.f);
        float4 o = y;
        if (rnd) {
            o.x = f2tf32r(y.x); o.y = f2tf32r(y.y);
            o.z = f2tf32r(y.z); o.w = f2tf32r(y.w);
        }
        ((float4*)out)[i] = o;
        if (out2) {
            float4 o2 = y;
            if (rnd2) {
                o2.x = f2tf32r(y.x); o2.y = f2tf32r(y.y);
                o2.z = f2tf32r(y.z); o2.w = f2tf32r(y.w);
            }
            ((float4*)out2)[row * ld2_4 + c4] = o2;
        }
    }
}

// ---------------------------------------------------------------------------
extern "C" void kernel_launch(void* const* d_in, const int* in_sizes, int n_in,
                              void* d_out, int out_size)
{
    const float* seq    = (const float*)d_in[0];
    const float* go     = (const float*)d_in[1];
    const int*   erow   = (const int*)  d_in[2];
    const int*   ecol   = (const int*)  d_in[3];
    const float* eval_  = (const float*)d_in[4];
    const float* mlp_w1 = (const float*)d_in[5];
    const float* mlp_b1 = (const float*)d_in[6];
    const float* mlp_w2 = (const float*)d_in[7];
    const float* mlp_b2 = (const float*)d_in[8];
    const float* gc1_w  = (const float*)d_in[9];
    const float* gc1_b  = (const float*)d_in[10];
    const float* gc2_w  = (const float*)d_in[11];
    const float* gc2_b  = (const float*)d_in[12];
    const float* se_w1  = (const float*)d_in[13];
    const float* se_b1  = (const float*)d_in[14];
    const float* se_w2  = (const float*)d_in[15];
    const float* se_b2  = (const float*)d_in[16];

    float* out  = (float*)d_out;
    float* hsem = out;
    float* hstr = out + (size_t)N_GO * NHID1;
    float* pred = out + (size_t)2 * N_GO * NHID1;

    float *t1, *g1, *s1, *g2, *s2, *u, *so, *cat, *goc, *seqc, *wt;
    cudaGetSymbolAddress((void**)&t1,   g_t1);
    cudaGetSymbolAddress((void**)&g1,   g_g1);
    cudaGetSymbolAddress((void**)&s1,   g_s1);
    cudaGetSymbolAddress((void**)&g2,   g_g2);
    cudaGetSymbolAddress((void**)&s2,   g_s2);
    cudaGetSymbolAddress((void**)&u,    g_u);
    cudaGetSymbolAddress((void**)&so,   g_so);
    cudaGetSymbolAddress((void**)&cat,  g_cat);
    cudaGetSymbolAddress((void**)&goc,  g_goc);
    cudaGetSymbolAddress((void**)&seqc, g_seqc);
    cudaGetSymbolAddress((void**)&wt,   g_wt);

    float* wt_mlp1 = wt + 0;        // [1024,512]
    float* wt_mlp2 = wt + 524288;   // [512,1024]
    float* wt_gc1  = wt + 1048576;  // [1024,512]
    float* wt_gc2  = wt + 1572864;  // [512,1024]
    float* wt_se1  = wt + 2097152;  // [1024,1280]
    float* wt_se2  = wt + 3407872;  // [1024,1024]

    cudaFuncSetAttribute(gemm_mma, cudaFuncAttributeMaxDynamicSharedMemorySize,
                         GEMM_SMEM_BYTES);

    const int T = 256;
    dim3 tb(32, 8);

    // pre-round inputs; transpose+round weights
    round_k<<<2048, T>>>(go,  goc,  (long)N_GO * GO_FEAT / 4);
    round_k<<<2048, T>>>(seq, seqc, (long)SEQ_B * SEQ_FEAT / 4);
    transpose_k<<<dim3(1024 / 32, 512 / 32),  tb>>>(mlp_w1, wt_mlp1, 512, 1024);
    transpose_k<<<dim3(512 / 32,  1024 / 32), tb>>>(mlp_w2, wt_mlp2, 1024, 512);
    transpose_k<<<dim3(1024 / 32, 512 / 32),  tb>>>(gc1_w,  wt_gc1,  512, 1024);
    transpose_k<<<dim3(512 / 32,  1024 / 32), tb>>>(gc2_w,  wt_gc2,  1024, 512);
    transpose_k<<<dim3(1024 / 32, 1280 / 32), tb>>>(se_w1,  wt_se1,  1280, 1024);
    transpose_k<<<dim3(1024 / 32, 1024 / 32), tb>>>(se_w2,  wt_se2,  1024, 1024);

    // zero spmm accumulators
    zero_kernel<<<4096, T>>>((float4*)s1, (long)N_GO * NHID0 / 4);
    zero_kernel<<<4096, T>>>((float4*)s2, (long)N_GO * NHID1 / 4);

    const int MT_GO  = cdiv(N_GO, 128);   // 313
    const int MT_SEQ = SEQ_B / 128;       // 32

    // semantic branch
    gemm_mma<<<dim3(NHID0 / 128, MT_GO), T, GEMM_SMEM_BYTES>>>(
        goc, wt_mlp1, mlp_b1, t1, nullptr, 0, N_GO, NHID0, GO_FEAT, 1, 1, 0);
    gemm_mma<<<dim3(NHID1 / 128, MT_GO), T, GEMM_SMEM_BYTES>>>(
        t1, wt_mlp2, mlp_b2, hsem, cat, 1024, N_GO, NHID1, NHID0, 0, 0, 1);

    // structure branch
    gemm_mma<<<dim3(NHID0 / 128, MT_GO), T, GEMM_SMEM_BYTES>>>(
        goc, wt_gc1, nullptr, g1, nullptr, 0, N_GO, NHID0, GO_FEAT, 0, 0, 0);
    spmm_kernel<<<dim3(N_EDGES * 32 / T, NHID0 / 128), T>>>(
        erow, ecol, eval_, g1, s1, N_EDGES, NHID0);
    bias_relu_k<<<4096, T>>>(s1, gc1_b, s1, 1, nullptr, 0, 0,
                             (long)N_GO * NHID0 / 4, NHID0 / 4);
    gemm_mma<<<dim3(NHID1 / 128, MT_GO), T, GEMM_SMEM_BYTES>>>(
        s1, wt_gc2, nullptr, g2, nullptr, 0, N_GO, NHID1, NHID0, 0, 0, 0);
    spmm_kernel<<<dim3(N_EDGES * 32 / T, NHID1 / 128), T>>>(
        erow, ecol, eval_, g2, s2, N_EDGES, NHID1);
    bias_relu_k<<<4096, T>>>(s2, gc2_b, hstr, 0, cat + 512, 256, 1,
                             (long)N_GO * NHID1 / 4, NHID1 / 4);

    // sequence encoder
    gemm_mma<<<dim3(NHID0 / 128, MT_SEQ), T, GEMM_SMEM_BYTES>>>(
        seqc, wt_se1, se_b1, u, nullptr, 0, SEQ_B, NHID0, SEQ_FEAT, 1, 1, 0);
    gemm_mma<<<dim3(NHID0 / 128, MT_SEQ), T, GEMM_SMEM_BYTES>>>(
        u, wt_se2, se_b2, so, nullptr, 0, SEQ_B, NHID0, NHID0, 0, 1, 0);

    // prediction: sigmoid(so[4096,1024] @ cat[40000,1024]^T)
    gemm_mma<<<dim3(MT_GO, MT_SEQ), T, GEMM_SMEM_BYTES>>>(
        so, cat, nullptr, pred, nullptr, 0, SEQ_B, N_GO, NHID0, 2, 0, 0);
}

// round 5
// speedup vs baseline: 2.8565x; 1.0017x over previous
#include <cuda_runtime.h>
#include <cstdint>
#include <math.h>

// ---------------------------------------------------------------------------
// GraphNeuralNetwork forward, GEMMs on mma.sync tf32 tensor cores with
// cp.async 3-stage pipelines (sm_80+ PTX path, valid under compute_103).
// All GEMM inputs are pre-rounded to tf32 so the GEMM copies bytes directly.
// R5: 4 warps x (64x64) warp tiles -> 1.0 LDS/MMA, single barrier per K-tile.
// ---------------------------------------------------------------------------

#define N_GO    40000
#define GO_FEAT 512
#define SEQ_FEAT 1280
#define NHID0   1024
#define NHID1   512
#define N_EDGES 640000
#define SEQ_B   4096

// ---------------- scratch (no runtime allocation allowed) ------------------
__device__ float g_t1[(size_t)N_GO * NHID0];
__device__ float g_g1[(size_t)N_GO * NHID0];
__device__ float g_s1[(size_t)N_GO * NHID0];
__device__ float g_g2[(size_t)N_GO * NHID1];
__device__ float g_s2[(size_t)N_GO * NHID1];
__device__ float g_u [(size_t)SEQ_B * NHID0];
__device__ float g_so[(size_t)SEQ_B * NHID0];
__device__ float g_cat[(size_t)N_GO * 1024];
__device__ float g_goc[(size_t)N_GO * GO_FEAT];    // tf32-rounded go
__device__ float g_seqc[(size_t)SEQ_B * SEQ_FEAT]; // tf32-rounded seq
__device__ float g_wt[4456448];                    // transposed+rounded weights

static inline int cdiv(int a, int b) { return (a + b - 1) / b; }

// ---------------------------------------------------------------------------
__device__ __forceinline__ float f2tf32r(float x) {
    uint32_t r;
    asm("cvt.rna.tf32.f32 %0, %1;" : "=r"(r) : "f"(x));
    return __uint_as_float(r);
}

__device__ __forceinline__ void mma_tf32(float c[4], const uint32_t a[4],
                                         const uint32_t b[2]) {
    asm volatile(
        "mma.sync.aligned.m16n8k8.row.col.f32.tf32.tf32.f32 "
        "{%0,%1,%2,%3}, {%4,%5,%6,%7}, {%8,%9}, {%0,%1,%2,%3};"
        : "+f"(c[0]), "+f"(c[1]), "+f"(c[2]), "+f"(c[3])
        : "r"(a[0]), "r"(a[1]), "r"(a[2]), "r"(a[3]), "r"(b[0]), "r"(b[1]));
}

__device__ __forceinline__ uint32_t smem_u32(const void* p) {
    uint32_t a;
    asm("{ .reg .u64 t; cvta.to.shared.u64 t, %1; cvt.u32.u64 %0, t; }"
        : "=r"(a) : "l"(p));
    return a;
}

__device__ __forceinline__ void cp_async16(uint32_t dst, const void* src, bool valid) {
    int sz = valid ? 16 : 0;
    asm volatile("cp.async.cg.shared.global [%0], [%1], 16, %2;"
                 :: "r"(dst), "l"(src), "r"(sz) : "memory");
}
#define CP_COMMIT() asm volatile("cp.async.commit_group;" ::: "memory")
#define CP_WAIT1()  asm volatile("cp.async.wait_group 1;" ::: "memory")

// ---------------------------------------------------------------------------
// GEMM: C[M,N] = act(A[M,K] @ B[N,K]^T + bias). Both operands row-major,
// K contiguous, values already tf32-rounded. CTA tile 128x128, K-tile 32,
// 4 warps (2x2), warp tile 64x64, 3-stage cp.async pipeline, pitch-36 SMEM.
// act: 0=none 1=relu 2=sigmoid. roundC/roundC2: tf32-round that output.
// Requirements: K % 32 == 0, N even.
// ---------------------------------------------------------------------------
#define PITCH 36
#define TILE_WORDS (128 * PITCH)
#define STAGE_WORDS (2 * TILE_WORDS)
#define NSTAGE 3
#define GEMM_SMEM_BYTES (NSTAGE * STAGE_WORDS * 4)   // 110592
#define GEMM_T 128

__global__ void __launch_bounds__(GEMM_T, 2) gemm_mma(
    const float* __restrict__ A, const float* __restrict__ B,
    const float* __restrict__ bias, float* __restrict__ C,
    float* __restrict__ C2, int ldc2,
    int M, int N, int K, int act, int roundC, int roundC2)
{
    extern __shared__ float sm[];
    const uint32_t smem_base = smem_u32(sm);

    const int tid  = threadIdx.x;
    const int wid  = tid >> 5;
    const int lane = tid & 31;
    const int g    = lane >> 2;
    const int tig  = lane & 3;
    const int wm   = wid >> 1;       // 0..1
    const int wn   = wid & 1;        // 0..1
    const int n0   = blockIdx.x * 128;
    const int m0   = blockIdx.y * 128;

    const int nkt = K >> 5;

    auto issue = [&](int kt) {
        if (kt < nkt) {
            const int k0 = kt << 5;
            const uint32_t sbase = smem_base + (uint32_t)(kt % NSTAGE) * (STAGE_WORDS * 4);
#pragma unroll
            for (int it = 0; it < 8; it++) {
                int idx = tid + it * GEMM_T;       // 0..1023
                int r   = idx >> 3;
                int k4  = (idx & 7) << 2;
                uint32_t da = sbase + (uint32_t)(r * PITCH + k4) * 4;
                cp_async16(da, A + (size_t)(m0 + r) * K + k0 + k4, (m0 + r) < M);
                cp_async16(da + TILE_WORDS * 4, B + (size_t)(n0 + r) * K + k0 + k4,
                           (n0 + r) < N);
            }
        }
        CP_COMMIT();
    };

    float acc[4][8][4];
#pragma unroll
    for (int i = 0; i < 4; i++)
#pragma unroll
        for (int j = 0; j < 8; j++)
#pragma unroll
            for (int t = 0; t < 4; t++) acc[i][j][t] = 0.f;

    issue(0);
    issue(1);

    const int arow = (wm * 64 + g) * PITCH;
    const int brow = (wn * 64 + g) * PITCH;

    for (int kt = 0; kt < nkt; kt++) {
        CP_WAIT1();
        __syncthreads();
        issue(kt + 2);

        const float* as = sm + (kt % NSTAGE) * STAGE_WORDS;
        const float* bs = as + TILE_WORDS;
#pragma unroll
        for (int kk = 0; kk < 4; kk++) {
            const int kc = kk * 8 + tig;
            uint32_t af[4][4];
#pragma unroll
            for (int i = 0; i < 4; i++) {
                int base = arow + i * 16 * PITCH;
                af[i][0] = __float_as_uint(as[base + kc]);
                af[i][1] = __float_as_uint(as[base + 8 * PITCH + kc]);
                af[i][2] = __float_as_uint(as[base + kc + 4]);
                af[i][3] = __float_as_uint(as[base + 8 * PITCH + kc + 4]);
            }
            uint32_t bf[8][2];
#pragma unroll
            for (int j = 0; j < 8; j++) {
                int base = brow + j * 8 * PITCH;
                bf[j][0] = __float_as_uint(bs[base + kc]);
                bf[j][1] = __float_as_uint(bs[base + kc + 4]);
            }
#pragma unroll
            for (int i = 0; i < 4; i++)
#pragma unroll
                for (int j = 0; j < 8; j++)
                    mma_tf32(acc[i][j], af[i], bf[j]);
        }
        // single top-of-loop barrier is sufficient: a warp at the next
        // iteration's barrier has finished this compute, so issue(kt+3)
        // overwriting stage kt%3 cannot race.
    }

    // ---- epilogue ----
#pragma unroll
    for (int i = 0; i < 4; i++) {
        const int r0 = m0 + wm * 64 + 16 * i + g;
#pragma unroll
        for (int j = 0; j < 8; j++) {
            const int cn = n0 + wn * 64 + 8 * j + 2 * tig;
            if (cn >= N) continue;
            float b0 = 0.f, b1 = 0.f;
            if (bias != nullptr) { b0 = bias[cn]; b1 = bias[cn + 1]; }
#pragma unroll
            for (int h = 0; h < 2; h++) {
                const int r = r0 + h * 8;
                if (r >= M) continue;
                float x0 = acc[i][j][2 * h]     + b0;
                float x1 = acc[i][j][2 * h + 1] + b1;
                if (act == 1) { x0 = fmaxf(x0, 0.f); x1 = fmaxf(x1, 0.f); }
                else if (act == 2) {
                    x0 = 1.f / (1.f + __expf(-x0));
                    x1 = 1.f / (1.f + __expf(-x1));
                }
                float c0 = roundC ? f2tf32r(x0) : x0;
                float c1 = roundC ? f2tf32r(x1) : x1;
                *(float2*)(C + (size_t)r * N + cn) = make_float2(c0, c1);
                if (C2) {
                    float d0 = roundC2 ? f2tf32r(x0) : x0;
                    float d1 = roundC2 ? f2tf32r(x1) : x1;
                    *(float2*)(C2 + (size_t)r * ldc2 + cn) = make_float2(d0, d1);
                }
            }
        }
    }
}

// ---------------------------------------------------------------------------
// transpose + tf32-round: out[c][r] = round(in[r][c])
// ---------------------------------------------------------------------------
__global__ void transpose_k(const float* __restrict__ in, float* __restrict__ out,
                            int R, int C)
{
    __shared__ float t[32][33];
    int bx = blockIdx.x * 32, by = blockIdx.y * 32;
    int x = bx + threadIdx.x;
    int y = by + threadIdx.y;
#pragma unroll
    for (int j = 0; j < 32; j += 8)
        if (y + j < R && x < C) t[threadIdx.y + j][threadIdx.x] = in[(size_t)(y + j) * C + x];
    __syncthreads();
    x = by + threadIdx.x;
    y = bx + threadIdx.y;
#pragma unroll
    for (int j = 0; j < 32; j += 8)
        if (y + j < C && x < R)
            out[(size_t)(y + j) * R + x] = f2tf32r(t[threadIdx.x][threadIdx.y + j]);
}

// elementwise tf32 rounding
__global__ void round_k(const float* __restrict__ in, float* __restrict__ out, long n4)
{
    long i = blockIdx.x * (long)blockDim.x + threadIdx.x;
    long stride = (long)gridDim.x * blockDim.x;
    for (; i < n4; i += stride) {
        float4 v = ((const float4*)in)[i];
        v.x = f2tf32r(v.x); v.y = f2tf32r(v.y);
        v.z = f2tf32r(v.z); v.w = f2tf32r(v.w);
        ((float4*)out)[i] = v;
    }
}

// ---------------------------------------------------------------------------
// SpMM (COO, float4 atomics): out[row] += val * x[col]
// ---------------------------------------------------------------------------
__global__ void spmm_kernel(const int* __restrict__ erow, const int* __restrict__ ecol,
                            const float* __restrict__ eval, const float* __restrict__ x,
                            float* __restrict__ out, int nEdges, int d)
{
    int gw = (blockIdx.x * blockDim.x + threadIdx.x) >> 5;
    if (gw >= nEdges) return;
    int lane = threadIdx.x & 31;
    int r = erow[gw];
    int c = ecol[gw];
    float v = eval[gw];
    int off = blockIdx.y * 128 + lane * 4;
    float4 xv = *(const float4*)(x + (size_t)c * d + off);
    float4 add = make_float4(v * xv.x, v * xv.y, v * xv.z, v * xv.w);
    atomicAdd((float4*)(out + (size_t)r * d + off), add);
}

__global__ void zero_kernel(float4* __restrict__ p, long n4)
{
    long i = blockIdx.x * (long)blockDim.x + threadIdx.x;
    long stride = (long)gridDim.x * blockDim.x;
    for (; i < n4; i += stride) p[i] = make_float4(0.f, 0.f, 0.f, 0.f);
}

// out = relu(in + bias) [optionally tf32-rounded]; optional second copy out2.
__global__ void bias_relu_k(const float* __restrict__ in, const float* __restrict__ b,
                            float* __restrict__ out, int rnd,
                            float* __restrict__ out2, int ld2_4, int rnd2,
                            long total4, int d4)
{
    long i = blockIdx.x * (long)blockDim.x + threadIdx.x;
    long stride = (long)gridDim.x * blockDim.x;
    for (; i < total4; i += stride) {
        int  c4  = (int)(i % d4);
        long row = i / d4;
        float4 x  = ((const float4*)in)[i];
        float4 bb = ((const float4*)b)[c4];
        float4 y;
        y.x = fmaxf(x.x + bb.x, 0.f);
        y.y = fmaxf(x.y + bb.y, 0.f);
        y.z = fmaxf(x.z + bb.z, 0.f);
        y.w = fmaxf(x.w + bb.w, 0.f);
        float4 o = y;
        if (rnd) {
            o.x = f2tf32r(y.x); o.y = f2tf32r(y.y);
            o.z = f2tf32r(y.z); o.w = f2tf32r(y.w);
        }
        ((float4*)out)[i] = o;
        if (out2) {
            float4 o2 = y;
            if (rnd2) {
                o2.x = f2tf32r(y.x); o2.y = f2tf32r(y.y);
                o2.z = f2tf32r(y.z); o2.w = f2tf32r(y.w);
            }
            ((float4*)out2)[row * ld2_4 + c4] = o2;
        }
    }
}

// ---------------------------------------------------------------------------
extern "C" void kernel_launch(void* const* d_in, const int* in_sizes, int n_in,
                              void* d_out, int out_size)
{
    const float* seq    = (const float*)d_in[0];
    const float* go     = (const float*)d_in[1];
    const int*   erow   = (const int*)  d_in[2];
    const int*   ecol   = (const int*)  d_in[3];
    const float* eval_  = (const float*)d_in[4];
    const float* mlp_w1 = (const float*)d_in[5];
    const float* mlp_b1 = (const float*)d_in[6];
    const float* mlp_w2 = (const float*)d_in[7];
    const float* mlp_b2 = (const float*)d_in[8];
    const float* gc1_w  = (const float*)d_in[9];
    const float* gc1_b  = (const float*)d_in[10];
    const float* gc2_w  = (const float*)d_in[11];
    const float* gc2_b  = (const float*)d_in[12];
    const float* se_w1  = (const float*)d_in[13];
    const float* se_b1  = (const float*)d_in[14];
    const float* se_w2  = (const float*)d_in[15];
    const float* se_b2  = (const float*)d_in[16];

    float* out  = (float*)d_out;
    float* hsem = out;
    float* hstr = out + (size_t)N_GO * NHID1;
    float* pred = out + (size_t)2 * N_GO * NHID1;

    float *t1, *g1, *s1, *g2, *s2, *u, *so, *cat, *goc, *seqc, *wt;
    cudaGetSymbolAddress((void**)&t1,   g_t1);
    cudaGetSymbolAddress((void**)&g1,   g_g1);
    cudaGetSymbolAddress((void**)&s1,   g_s1);
    cudaGetSymbolAddress((void**)&g2,   g_g2);
    cudaGetSymbolAddress((void**)&s2,   g_s2);
    cudaGetSymbolAddress((void**)&u,    g_u);
    cudaGetSymbolAddress((void**)&so,   g_so);
    cudaGetSymbolAddress((void**)&cat,  g_cat);
    cudaGetSymbolAddress((void**)&goc,  g_goc);
    cudaGetSymbolAddress((void**)&seqc, g_seqc);
    cudaGetSymbolAddress((void**)&wt,   g_wt);

    float* wt_mlp1 = wt + 0;        // [1024,512]
    float* wt_mlp2 = wt + 524288;   // [512,1024]
    float* wt_gc1  = wt + 1048576;  // [1024,512]
    float* wt_gc2  = wt + 1572864;  // [512,1024]
    float* wt_se1  = wt + 2097152;  // [1024,1280]
    float* wt_se2  = wt + 3407872;  // [1024,1024]

    cudaFuncSetAttribute(gemm_mma, cudaFuncAttributeMaxDynamicSharedMemorySize,
                         GEMM_SMEM_BYTES);

    const int T = 256;
    dim3 tb(32, 8);

    // pre-round inputs; transpose+round weights
    round_k<<<2048, T>>>(go,  goc,  (long)N_GO * GO_FEAT / 4);
    round_k<<<2048, T>>>(seq, seqc, (long)SEQ_B * SEQ_FEAT / 4);
    transpose_k<<<dim3(1024 / 32, 512 / 32),  tb>>>(mlp_w1, wt_mlp1, 512, 1024);
    transpose_k<<<dim3(512 / 32,  1024 / 32), tb>>>(mlp_w2, wt_mlp2, 1024, 512);
    transpose_k<<<dim3(1024 / 32, 512 / 32),  tb>>>(gc1_w,  wt_gc1,  512, 1024);
    transpose_k<<<dim3(512 / 32,  1024 / 32), tb>>>(gc2_w,  wt_gc2,  1024, 512);
    transpose_k<<<dim3(1024 / 32, 1280 / 32), tb>>>(se_w1,  wt_se1,  1280, 1024);
    transpose_k<<<dim3(1024 / 32, 1024 / 32), tb>>>(se_w2,  wt_se2,  1024, 1024);

    // zero spmm accumulators
    zero_kernel<<<4096, T>>>((float4*)s1, (long)N_GO * NHID0 / 4);
    zero_kernel<<<4096, T>>>((float4*)s2, (long)N_GO * NHID1 / 4);

    const int MT_GO  = cdiv(N_GO, 128);   // 313
    const int MT_SEQ = SEQ_B / 128;       // 32

    // semantic branch
    gemm_mma<<<dim3(NHID0 / 128, MT_GO), GEMM_T, GEMM_SMEM_BYTES>>>(
        goc, wt_mlp1, mlp_b1, t1, nullptr, 0, N_GO, NHID0, GO_FEAT, 1, 1, 0);
    gemm_mma<<<dim3(NHID1 / 128, MT_GO), GEMM_T, GEMM_SMEM_BYTES>>>(
        t1, wt_mlp2, mlp_b2, hsem, cat, 1024, N_GO, NHID1, NHID0, 0, 0, 1);

    // structure branch
    gemm_mma<<<dim3(NHID0 / 128, MT_GO), GEMM_T, GEMM_SMEM_BYTES>>>(
        goc, wt_gc1, nullptr, g1, nullptr, 0, N_GO, NHID0, GO_FEAT, 0, 0, 0);
    spmm_kernel<<<dim3(N_EDGES * 32 / T, NHID0 / 128), T>>>(
        erow, ecol, eval_, g1, s1, N_EDGES, NHID0);
    bias_relu_k<<<4096, T>>>(s1, gc1_b, s1, 1, nullptr, 0, 0,
                             (long)N_GO * NHID0 / 4, NHID0 / 4);
    gemm_mma<<<dim3(NHID1 / 128, MT_GO), GEMM_T, GEMM_SMEM_BYTES>>>(
        s1, wt_gc2, nullptr, g2, nullptr, 0, N_GO, NHID1, NHID0, 0, 0, 0);
    spmm_kernel<<<dim3(N_EDGES * 32 / T, NHID1 / 128), T>>>(
        erow, ecol, eval_, g2, s2, N_EDGES, NHID1);
    bias_relu_k<<<4096, T>>>(s2, gc2_b, hstr, 0, cat + 512, 256, 1,
                             (long)N_GO * NHID1 / 4, NHID1 / 4);

    // sequence encoder
    gemm_mma<<<dim3(NHID0 / 128, MT_SEQ), GEMM_T, GEMM_SMEM_BYTES>>>(
        seqc, wt_se1, se_b1, u, nullptr, 0, SEQ_B, NHID0, SEQ_FEAT, 1, 1, 0);
    gemm_mma<<<dim3(NHID0 / 128, MT_SEQ), GEMM_T, GEMM_SMEM_BYTES>>>(
        u, wt_se2, se_b2, so, nullptr, 0, SEQ_B, NHID0, NHID0, 0, 1, 0);

    // prediction: sigmoid(so[4096,1024] @ cat[40000,1024]^T)
    gemm_mma<<<dim3(MT_GO, MT_SEQ), GEMM_T, GEMM_SMEM_BYTES>>>(
        so, cat, nullptr, pred, nullptr, 0, SEQ_B, N_GO, NHID0, 2, 0, 0);
}

// round 6
// speedup vs baseline: 4.7924x; 1.6777x over previous
#include <cuda_runtime.h>
#include <cuda_fp16.h>
#include <cstdint>
#include <math.h>

// ---------------------------------------------------------------------------
// GraphNeuralNetwork forward. GEMMs on mma.sync fp16 (m16n8k16, fp32 accum)
// -- 2x the tf32 HMMA rate with identical 10-bit mantissa inputs.
// Layer-1 graph conv reassociated: spmm(A, GO@W) == (spmm(A,GO))@W, so both
// spmms run at d=512 and read fp16.
// ---------------------------------------------------------------------------

#define N_GO    40000
#define GO_FEAT 512
#define SEQ_FEAT 1280
#define NHID0   1024
#define NHID1   512
#define N_EDGES 640000
#define SEQ_B   4096

// ---------------- scratch (no runtime allocation allowed) ------------------
__device__ __half g_goh [(size_t)N_GO * GO_FEAT];
__device__ __half g_seqh[(size_t)SEQ_B * SEQ_FEAT];
__device__ __half g_t1h [(size_t)N_GO * NHID0];
__device__ __half g_xh  [(size_t)N_GO * NHID0];
__device__ __half g_g2h [(size_t)N_GO * NHID1];
__device__ __half g_uh  [(size_t)SEQ_B * NHID0];
__device__ __half g_soh [(size_t)SEQ_B * NHID0];
__device__ __half g_cath[(size_t)N_GO * 1024];
__device__ __half g_sp1h[(size_t)N_GO * NHID1];
__device__ float  g_s1  [(size_t)N_GO * NHID1];
__device__ float  g_s2  [(size_t)N_GO * NHID1];
__device__ __half g_wth[4456448];  // transposed half weights arena

static inline int cdiv(int a, int b) { return (a + b - 1) / b; }

// ---------------------------------------------------------------------------
__device__ __forceinline__ uint32_t smem_u32(const void* p) {
    uint32_t a;
    asm("{ .reg .u64 t; cvta.to.shared.u64 t, %1; cvt.u32.u64 %0, t; }"
        : "=r"(a) : "l"(p));
    return a;
}

__device__ __forceinline__ void mma_f16(float c[4], const uint32_t a[4],
                                        const uint32_t b[2]) {
    asm volatile(
        "mma.sync.aligned.m16n8k16.row.col.f32.f16.f16.f32 "
        "{%0,%1,%2,%3}, {%4,%5,%6,%7}, {%8,%9}, {%0,%1,%2,%3};"
        : "+f"(c[0]), "+f"(c[1]), "+f"(c[2]), "+f"(c[3])
        : "r"(a[0]), "r"(a[1]), "r"(a[2]), "r"(a[3]), "r"(b[0]), "r"(b[1]));
}

__device__ __forceinline__ void cp_async16(uint32_t dst, const void* src, bool valid) {
    int sz = valid ? 16 : 0;
    asm volatile("cp.async.cg.shared.global [%0], [%1], 16, %2;"
                 :: "r"(dst), "l"(src), "r"(sz) : "memory");
}
#define CP_COMMIT() asm volatile("cp.async.commit_group;" ::: "memory")
#define CP_WAIT2()  asm volatile("cp.async.wait_group 2;" ::: "memory")

// ---------------------------------------------------------------------------
// fp16 GEMM: C[M,N] = act(A[M,K] @ B[N,K]^T + bias). A,B half row-major
// (K contiguous), fp32 accumulate. CTA 128x128, K-tile 32, 4 warps (2x2,
// warp tile 64x64), 4-stage cp.async, pitch 40 halfs (20 words; conflict-free
// fragment LDS: bank = g*20+tig distinct mod 32).
// act: 0=none 1=relu 2=sigmoid. C half if cHalf else float.
// Optional C2 (half, row stride ldc2). swapxy: blockIdx.x indexes M.
// Requirements: K % 32 == 0, N even.
// ---------------------------------------------------------------------------
#define PW 20                         // 32-bit words per smem row
#define TILE_B 10240                  // 128 rows * 80 bytes
#define STAGE_B (2 * TILE_B)          // A + B
#define NSTAGE 4
#define GEMM_SMEM_BYTES (NSTAGE * STAGE_B)   // 81920
#define GEMM_T 128

__global__ void __launch_bounds__(GEMM_T, 2) gemm_h(
    const __half* __restrict__ A, const __half* __restrict__ B,
    const float* __restrict__ bias, void* __restrict__ Cv, int cHalf,
    __half* __restrict__ C2, int ldc2,
    int M, int N, int K, int act, int swapxy)
{
    extern __shared__ __align__(16) char smc[];
    const uint32_t smem_base = smem_u32(smc);

    const int tid  = threadIdx.x;
    const int wid  = tid >> 5;
    const int lane = tid & 31;
    const int g    = lane >> 2;
    const int tig  = lane & 3;
    const int wm   = wid >> 1;
    const int wn   = wid & 1;
    const int m0   = (swapxy ? blockIdx.x : blockIdx.y) * 128;
    const int n0   = (swapxy ? blockIdx.y : blockIdx.x) * 128;

    const int nkt = K >> 5;

    auto issue = [&](int kt) {
        if (kt < nkt) {
            const int k0 = kt << 5;
            const uint32_t sbase = smem_base + (uint32_t)(kt % NSTAGE) * STAGE_B;
#pragma unroll
            for (int it = 0; it < 4; it++) {
                int idx = tid + it * GEMM_T;   // 0..511
                int r   = idx >> 2;            // 0..127
                int c   = idx & 3;             // 16B chunk
                uint32_t da = sbase + (uint32_t)(r * 80 + c * 16);
                cp_async16(da, A + (size_t)(m0 + r) * K + k0 + c * 8, (m0 + r) < M);
                cp_async16(da + TILE_B, B + (size_t)(n0 + r) * K + k0 + c * 8,
                           (n0 + r) < N);
            }
        }
        CP_COMMIT();
    };

    float acc[4][8][4];
#pragma unroll
    for (int i = 0; i < 4; i++)
#pragma unroll
        for (int j = 0; j < 8; j++)
#pragma unroll
            for (int t = 0; t < 4; t++) acc[i][j][t] = 0.f;

    issue(0); issue(1); issue(2);

    const int arow = (wm * 64 + g) * PW;
    const int brow = (wn * 64 + g) * PW;

    for (int kt = 0; kt < nkt; kt++) {
        CP_WAIT2();
        __syncthreads();
        issue(kt + 3);

        const uint32_t* as = (const uint32_t*)(smc + (kt % NSTAGE) * STAGE_B);
        const uint32_t* bs = as + TILE_B / 4;
#pragma unroll
        for (int kk = 0; kk < 2; kk++) {
            const int ko = kk * 8 + tig;
            uint32_t af[4][4];
#pragma unroll
            for (int i = 0; i < 4; i++) {
                int base = arow + i * 16 * PW;
                af[i][0] = as[base + ko];
                af[i][1] = as[base + 8 * PW + ko];
                af[i][2] = as[base + ko + 4];
                af[i][3] = as[base + 8 * PW + ko + 4];
            }
            uint32_t bf[8][2];
#pragma unroll
            for (int j = 0; j < 8; j++) {
                int base = brow + j * 8 * PW;
                bf[j][0] = bs[base + ko];
                bf[j][1] = bs[base + ko + 4];
            }
#pragma unroll
            for (int i = 0; i < 4; i++)
#pragma unroll
                for (int j = 0; j < 8; j++)
                    mma_f16(acc[i][j], af[i], bf[j]);
        }
    }

    // ---- epilogue ----
#pragma unroll
    for (int i = 0; i < 4; i++) {
        const int r0 = m0 + wm * 64 + 16 * i + g;
#pragma unroll
        for (int j = 0; j < 8; j++) {
            const int cn = n0 + wn * 64 + 8 * j + 2 * tig;
            if (cn >= N) continue;
            float b0 = 0.f, b1 = 0.f;
            if (bias != nullptr) { b0 = bias[cn]; b1 = bias[cn + 1]; }
#pragma unroll
            for (int h = 0; h < 2; h++) {
                const int r = r0 + h * 8;
                if (r >= M) continue;
                float x0 = acc[i][j][2 * h]     + b0;
                float x1 = acc[i][j][2 * h + 1] + b1;
                if (act == 1) { x0 = fmaxf(x0, 0.f); x1 = fmaxf(x1, 0.f); }
                else if (act == 2) {
                    x0 = 1.f / (1.f + __expf(-x0));
                    x1 = 1.f / (1.f + __expf(-x1));
                }
                if (cHalf)
                    *(__half2*)((__half*)Cv + (size_t)r * N + cn) =
                        __floats2half2_rn(x0, x1);
                else
                    *(float2*)((float*)Cv + (size_t)r * N + cn) =
                        make_float2(x0, x1);
                if (C2)
                    *(__half2*)(C2 + (size_t)r * ldc2 + cn) =
                        __floats2half2_rn(x0, x1);
            }
        }
    }
}

// ---------------------------------------------------------------------------
// transpose + half-round: out[c][r] = half(in[r][c])
// ---------------------------------------------------------------------------
__global__ void transpose_h(const float* __restrict__ in, __half* __restrict__ out,
                            int R, int C)
{
    __shared__ float t[32][33];
    int bx = blockIdx.x * 32, by = blockIdx.y * 32;
    int x = bx + threadIdx.x;
    int y = by + threadIdx.y;
#pragma unroll
    for (int j = 0; j < 32; j += 8)
        if (y + j < R && x < C) t[threadIdx.y + j][threadIdx.x] = in[(size_t)(y + j) * C + x];
    __syncthreads();
    x = by + threadIdx.x;
    y = bx + threadIdx.y;
#pragma unroll
    for (int j = 0; j < 32; j += 8)
        if (y + j < C && x < R)
            out[(size_t)(y + j) * R + x] = __float2half_rn(t[threadIdx.x][threadIdx.y + j]);
}

// fp32 -> fp16 elementwise
__global__ void conv_h(const float* __restrict__ in, __half* __restrict__ out, long n4)
{
    long i = blockIdx.x * (long)blockDim.x + threadIdx.x;
    long stride = (long)gridDim.x * blockDim.x;
    for (; i < n4; i += stride) {
        float4 v = ((const float4*)in)[i];
        ((__half2*)out)[2 * i]     = __floats2half2_rn(v.x, v.y);
        ((__half2*)out)[2 * i + 1] = __floats2half2_rn(v.z, v.w);
    }
}

// ---------------------------------------------------------------------------
// SpMM (COO): out[row] += val * x[col], x in fp16, accumulate fp32 atomics.
// One warp per edge per 128-column chunk.
// ---------------------------------------------------------------------------
__global__ void spmm_h(const int* __restrict__ erow, const int* __restrict__ ecol,
                       const float* __restrict__ eval, const __half* __restrict__ x,
                       float* __restrict__ out, int nEdges, int d)
{
    int gw = (blockIdx.x * blockDim.x + threadIdx.x) >> 5;
    if (gw >= nEdges) return;
    int lane = threadIdx.x & 31;
    int r = erow[gw];
    int c = ecol[gw];
    float v = eval[gw];
    int off = blockIdx.y * 128 + lane * 4;
    const __half2* xp = (const __half2*)(x + (size_t)c * d + off);
    float2 f0 = __half22float2(xp[0]);
    float2 f1 = __half22float2(xp[1]);
    float4 add = make_float4(v * f0.x, v * f0.y, v * f1.x, v * f1.y);
    atomicAdd((float4*)(out + (size_t)r * d + off), add);
}

__global__ void zero_kernel(float4* __restrict__ p, long n4)
{
    long i = blockIdx.x * (long)blockDim.x + threadIdx.x;
    long stride = (long)gridDim.x * blockDim.x;
    for (; i < n4; i += stride) p[i] = make_float4(0.f, 0.f, 0.f, 0.f);
}

// hstr = relu(s2 + gc2_b) (fp32) and half copy into cat[:, 512:1024]
__global__ void bias_relu_out(const float* __restrict__ in, const float* __restrict__ b,
                              float* __restrict__ outF, __half* __restrict__ outH,
                              long total4, int d4)
{
    long i = blockIdx.x * (long)blockDim.x + threadIdx.x;
    long stride = (long)gridDim.x * blockDim.x;
    for (; i < total4; i += stride) {
        int  c4  = (int)(i % d4);
        long row = i / d4;
        float4 x  = ((const float4*)in)[i];
        float4 bb = ((const float4*)b)[c4];
        float4 y;
        y.x = fmaxf(x.x + bb.x, 0.f);
        y.y = fmaxf(x.y + bb.y, 0.f);
        y.z = fmaxf(x.z + bb.z, 0.f);
        y.w = fmaxf(x.w + bb.w, 0.f);
        ((float4*)outF)[i] = y;
        __half2* hp = (__half2*)(outH + row * 1024 + 512 + c4 * 4);
        hp[0] = __floats2half2_rn(y.x, y.y);
        hp[1] = __floats2half2_rn(y.z, y.w);
    }
}

// ---------------------------------------------------------------------------
extern "C" void kernel_launch(void* const* d_in, const int* in_sizes, int n_in,
                              void* d_out, int out_size)
{
    const float* seq    = (const float*)d_in[0];
    const float* go     = (const float*)d_in[1];
    const int*   erow   = (const int*)  d_in[2];
    const int*   ecol   = (const int*)  d_in[3];
    const float* eval_  = (const float*)d_in[4];
    const float* mlp_w1 = (const float*)d_in[5];
    const float* mlp_b1 = (const float*)d_in[6];
    const float* mlp_w2 = (const float*)d_in[7];
    const float* mlp_b2 = (const float*)d_in[8];
    const float* gc1_w  = (const float*)d_in[9];
    const float* gc1_b  = (const float*)d_in[10];
    const float* gc2_w  = (const float*)d_in[11];
    const float* gc2_b  = (const float*)d_in[12];
    const float* se_w1  = (const float*)d_in[13];
    const float* se_b1  = (const float*)d_in[14];
    const float* se_w2  = (const float*)d_in[15];
    const float* se_b2  = (const float*)d_in[16];

    float* out  = (float*)d_out;
    float* hsem = out;
    float* hstr = out + (size_t)N_GO * NHID1;
    float* pred = out + (size_t)2 * N_GO * NHID1;

    __half *goh, *seqh, *t1h, *xh, *g2h, *uh, *soh, *cath, *sp1h, *wth;
    float *s1, *s2;
    cudaGetSymbolAddress((void**)&goh,  g_goh);
    cudaGetSymbolAddress((void**)&seqh, g_seqh);
    cudaGetSymbolAddress((void**)&t1h,  g_t1h);
    cudaGetSymbolAddress((void**)&xh,   g_xh);
    cudaGetSymbolAddress((void**)&g2h,  g_g2h);
    cudaGetSymbolAddress((void**)&uh,   g_uh);
    cudaGetSymbolAddress((void**)&soh,  g_soh);
    cudaGetSymbolAddress((void**)&cath, g_cath);
    cudaGetSymbolAddress((void**)&sp1h, g_sp1h);
    cudaGetSymbolAddress((void**)&s1,   g_s1);
    cudaGetSymbolAddress((void**)&s2,   g_s2);
    cudaGetSymbolAddress((void**)&wth,  g_wth);

    __half* wt_mlp1 = wth + 0;        // [1024,512]
    __half* wt_mlp2 = wth + 524288;   // [512,1024]
    __half* wt_gc1  = wth + 1048576;  // [1024,512]
    __half* wt_gc2  = wth + 1572864;  // [512,1024]
    __half* wt_se1  = wth + 2097152;  // [1024,1280]
    __half* wt_se2  = wth + 3407872;  // [1024,1024]

    cudaFuncSetAttribute(gemm_h, cudaFuncAttributeMaxDynamicSharedMemorySize,
                         GEMM_SMEM_BYTES);

    const int T = 256;
    dim3 tb(32, 8);

    // input conversion + weight transpose->half
    conv_h<<<2048, T>>>(go,  goh,  (long)N_GO * GO_FEAT / 4);
    conv_h<<<2048, T>>>(seq, seqh, (long)SEQ_B * SEQ_FEAT / 4);
    transpose_h<<<dim3(1024 / 32, 512 / 32),  tb>>>(mlp_w1, wt_mlp1, 512, 1024);
    transpose_h<<<dim3(512 / 32,  1024 / 32), tb>>>(mlp_w2, wt_mlp2, 1024, 512);
    transpose_h<<<dim3(1024 / 32, 512 / 32),  tb>>>(gc1_w,  wt_gc1,  512, 1024);
    transpose_h<<<dim3(512 / 32,  1024 / 32), tb>>>(gc2_w,  wt_gc2,  1024, 512);
    transpose_h<<<dim3(1024 / 32, 1280 / 32), tb>>>(se_w1,  wt_se1,  1280, 1024);
    transpose_h<<<dim3(1024 / 32, 1024 / 32), tb>>>(se_w2,  wt_se2,  1024, 1024);

    // zero spmm accumulators (both d=512 now)
    zero_kernel<<<2048, T>>>((float4*)s1, (long)N_GO * NHID1 / 4);
    zero_kernel<<<2048, T>>>((float4*)s2, (long)N_GO * NHID1 / 4);

    const int MT_GO  = cdiv(N_GO, 128);   // 313
    const int MT_SEQ = SEQ_B / 128;       // 32

    // structure branch: spmm first (reassociated), then GEMM w/ fused bias+relu
    spmm_h<<<dim3(N_EDGES * 32 / T, GO_FEAT / 128), T>>>(
        erow, ecol, eval_, goh, s1, N_EDGES, GO_FEAT);
    conv_h<<<2048, T>>>(s1, sp1h, (long)N_GO * NHID1 / 4);
    gemm_h<<<dim3(NHID0 / 128, MT_GO), GEMM_T, GEMM_SMEM_BYTES>>>(
        sp1h, wt_gc1, gc1_b, xh, 1, nullptr, 0, N_GO, NHID0, GO_FEAT, 1, 0);
    gemm_h<<<dim3(NHID1 / 128, MT_GO), GEMM_T, GEMM_SMEM_BYTES>>>(
        xh, wt_gc2, nullptr, g2h, 1, nullptr, 0, N_GO, NHID1, NHID0, 0, 0);
    spmm_h<<<dim3(N_EDGES * 32 / T, NHID1 / 128), T>>>(
        erow, ecol, eval_, g2h, s2, N_EDGES, NHID1);
    bias_relu_out<<<2048, T>>>(s2, gc2_b, hstr, cath,
                               (long)N_GO * NHID1 / 4, NHID1 / 4);

    // semantic branch
    gemm_h<<<dim3(NHID0 / 128, MT_GO), GEMM_T, GEMM_SMEM_BYTES>>>(
        goh, wt_mlp1, mlp_b1, t1h, 1, nullptr, 0, N_GO, NHID0, GO_FEAT, 1, 0);
    gemm_h<<<dim3(NHID1 / 128, MT_GO), GEMM_T, GEMM_SMEM_BYTES>>>(
        t1h, wt_mlp2, mlp_b2, hsem, 0, cath, 1024, N_GO, NHID1, NHID0, 0, 0);

    // sequence encoder
    gemm_h<<<dim3(NHID0 / 128, MT_SEQ), GEMM_T, GEMM_SMEM_BYTES>>>(
        seqh, wt_se1, se_b1, uh, 1, nullptr, 0, SEQ_B, NHID0, SEQ_FEAT, 1, 0);
    gemm_h<<<dim3(NHID0 / 128, MT_SEQ), GEMM_T, GEMM_SMEM_BYTES>>>(
        uh, wt_se2, se_b2, soh, 1, nullptr, 0, SEQ_B, NHID0, NHID0, 0, 0);

    // prediction: sigmoid(soh[4096,1024] @ cath[40000,1024]^T), grid m-fastest
    gemm_h<<<dim3(MT_SEQ, MT_GO), GEMM_T, GEMM_SMEM_BYTES>>>(
        soh, cath, nullptr, pred, 0, nullptr, 0, SEQ_B, N_GO, NHID0, 2, 1);
}

// round 7
// speedup vs baseline: 4.9373x; 1.0302x over previous
#include <cuda_runtime.h>
#include <cuda_fp16.h>
#include <cstdint>
#include <math.h>

// ---------------------------------------------------------------------------
// GraphNeuralNetwork forward. GEMMs on mma.sync fp16 (m16n8k16, fp32 accum).
// R7: captured fork/join -- structure chain (spmm-heavy, memory-bound) runs
// concurrently with semantic+sequence GEMM chain (tensor-bound).
// ---------------------------------------------------------------------------

#define N_GO    40000
#define GO_FEAT 512
#define SEQ_FEAT 1280
#define NHID0   1024
#define NHID1   512
#define N_EDGES 640000
#define SEQ_B   4096

// ---------------- scratch (no runtime allocation allowed) ------------------
__device__ __half g_goh [(size_t)N_GO * GO_FEAT];
__device__ __half g_seqh[(size_t)SEQ_B * SEQ_FEAT];
__device__ __half g_t1h [(size_t)N_GO * NHID0];
__device__ __half g_xh  [(size_t)N_GO * NHID0];
__device__ __half g_g2h [(size_t)N_GO * NHID1];
__device__ __half g_uh  [(size_t)SEQ_B * NHID0];
__device__ __half g_soh [(size_t)SEQ_B * NHID0];
__device__ __half g_cath[(size_t)N_GO * 1024];
__device__ __half g_sp1h[(size_t)N_GO * NHID1];
__device__ float  g_s1  [(size_t)N_GO * NHID1];
__device__ float  g_s2  [(size_t)N_GO * NHID1];
__device__ __half g_wth[4456448];  // transposed half weights arena

static inline int cdiv(int a, int b) { return (a + b - 1) / b; }

// ---------------------------------------------------------------------------
__device__ __forceinline__ uint32_t smem_u32(const void* p) {
    uint32_t a;
    asm("{ .reg .u64 t; cvta.to.shared.u64 t, %1; cvt.u32.u64 %0, t; }"
        : "=r"(a) : "l"(p));
    return a;
}

__device__ __forceinline__ void mma_f16(float c[4], const uint32_t a[4],
                                        const uint32_t b[2]) {
    asm volatile(
        "mma.sync.aligned.m16n8k16.row.col.f32.f16.f16.f32 "
        "{%0,%1,%2,%3}, {%4,%5,%6,%7}, {%8,%9}, {%0,%1,%2,%3};"
        : "+f"(c[0]), "+f"(c[1]), "+f"(c[2]), "+f"(c[3])
        : "r"(a[0]), "r"(a[1]), "r"(a[2]), "r"(a[3]), "r"(b[0]), "r"(b[1]));
}

__device__ __forceinline__ void cp_async16(uint32_t dst, const void* src, bool valid) {
    int sz = valid ? 16 : 0;
    asm volatile("cp.async.cg.shared.global [%0], [%1], 16, %2;"
                 :: "r"(dst), "l"(src), "r"(sz) : "memory");
}
#define CP_COMMIT() asm volatile("cp.async.commit_group;" ::: "memory")
#define CP_WAIT2()  asm volatile("cp.async.wait_group 2;" ::: "memory")

// ---------------------------------------------------------------------------
// fp16 GEMM: C[M,N] = act(A[M,K] @ B[N,K]^T + bias). CTA 128x128, K-tile 32,
// 4 warps (2x2, warp tile 64x64), 4-stage cp.async, pitch 40 halfs.
// act: 0=none 1=relu 2=sigmoid. C half if cHalf else float.
// Optional C2 (half, row stride ldc2). swapxy: blockIdx.x indexes M.
// ---------------------------------------------------------------------------
#define PW 20
#define TILE_B 10240
#define STAGE_B (2 * TILE_B)
#define NSTAGE 4
#define GEMM_SMEM_BYTES (NSTAGE * STAGE_B)   // 81920
#define GEMM_T 128

__global__ void __launch_bounds__(GEMM_T, 2) gemm_h(
    const __half* __restrict__ A, const __half* __restrict__ B,
    const float* __restrict__ bias, void* __restrict__ Cv, int cHalf,
    __half* __restrict__ C2, int ldc2,
    int M, int N, int K, int act, int swapxy)
{
    extern __shared__ __align__(16) char smc[];
    const uint32_t smem_base = smem_u32(smc);

    const int tid  = threadIdx.x;
    const int wid  = tid >> 5;
    const int lane = tid & 31;
    const int g    = lane >> 2;
    const int tig  = lane & 3;
    const int wm   = wid >> 1;
    const int wn   = wid & 1;
    const int m0   = (swapxy ? blockIdx.x : blockIdx.y) * 128;
    const int n0   = (swapxy ? blockIdx.y : blockIdx.x) * 128;

    const int nkt = K >> 5;

    auto issue = [&](int kt) {
        if (kt < nkt) {
            const int k0 = kt << 5;
            const uint32_t sbase = smem_base + (uint32_t)(kt % NSTAGE) * STAGE_B;
#pragma unroll
            for (int it = 0; it < 4; it++) {
                int idx = tid + it * GEMM_T;
                int r   = idx >> 2;
                int c   = idx & 3;
                uint32_t da = sbase + (uint32_t)(r * 80 + c * 16);
                cp_async16(da, A + (size_t)(m0 + r) * K + k0 + c * 8, (m0 + r) < M);
                cp_async16(da + TILE_B, B + (size_t)(n0 + r) * K + k0 + c * 8,
                           (n0 + r) < N);
            }
        }
        CP_COMMIT();
    };

    float acc[4][8][4];
#pragma unroll
    for (int i = 0; i < 4; i++)
#pragma unroll
        for (int j = 0; j < 8; j++)
#pragma unroll
            for (int t = 0; t < 4; t++) acc[i][j][t] = 0.f;

    issue(0); issue(1); issue(2);

    const int arow = (wm * 64 + g) * PW;
    const int brow = (wn * 64 + g) * PW;

    for (int kt = 0; kt < nkt; kt++) {
        CP_WAIT2();
        __syncthreads();
        issue(kt + 3);

        const uint32_t* as = (const uint32_t*)(smc + (kt % NSTAGE) * STAGE_B);
        const uint32_t* bs = as + TILE_B / 4;
#pragma unroll
        for (int kk = 0; kk < 2; kk++) {
            const int ko = kk * 8 + tig;
            uint32_t af[4][4];
#pragma unroll
            for (int i = 0; i < 4; i++) {
                int base = arow + i * 16 * PW;
                af[i][0] = as[base + ko];
                af[i][1] = as[base + 8 * PW + ko];
                af[i][2] = as[base + ko + 4];
                af[i][3] = as[base + 8 * PW + ko + 4];
            }
            uint32_t bf[8][2];
#pragma unroll
            for (int j = 0; j < 8; j++) {
                int base = brow + j * 8 * PW;
                bf[j][0] = bs[base + ko];
                bf[j][1] = bs[base + ko + 4];
            }
#pragma unroll
            for (int i = 0; i < 4; i++)
#pragma unroll
                for (int j = 0; j < 8; j++)
                    mma_f16(acc[i][j], af[i], bf[j]);
        }
    }

    // ---- epilogue ----
#pragma unroll
    for (int i = 0; i < 4; i++) {
        const int r0 = m0 + wm * 64 + 16 * i + g;
#pragma unroll
        for (int j = 0; j < 8; j++) {
            const int cn = n0 + wn * 64 + 8 * j + 2 * tig;
            if (cn >= N) continue;
            float b0 = 0.f, b1 = 0.f;
            if (bias != nullptr) { b0 = bias[cn]; b1 = bias[cn + 1]; }
#pragma unroll
            for (int h = 0; h < 2; h++) {
                const int r = r0 + h * 8;
                if (r >= M) continue;
                float x0 = acc[i][j][2 * h]     + b0;
                float x1 = acc[i][j][2 * h + 1] + b1;
                if (act == 1) { x0 = fmaxf(x0, 0.f); x1 = fmaxf(x1, 0.f); }
                else if (act == 2) {
                    x0 = 1.f / (1.f + __expf(-x0));
                    x1 = 1.f / (1.f + __expf(-x1));
                }
                if (cHalf)
                    *(__half2*)((__half*)Cv + (size_t)r * N + cn) =
                        __floats2half2_rn(x0, x1);
                else
                    *(float2*)((float*)Cv + (size_t)r * N + cn) =
                        make_float2(x0, x1);
                if (C2)
                    *(__half2*)(C2 + (size_t)r * ldc2 + cn) =
                        __floats2half2_rn(x0, x1);
            }
        }
    }
}

// ---------------------------------------------------------------------------
__global__ void transpose_h(const float* __restrict__ in, __half* __restrict__ out,
                            int R, int C)
{
    __shared__ float t[32][33];
    int bx = blockIdx.x * 32, by = blockIdx.y * 32;
    int x = bx + threadIdx.x;
    int y = by + threadIdx.y;
#pragma unroll
    for (int j = 0; j < 32; j += 8)
        if (y + j < R && x < C) t[threadIdx.y + j][threadIdx.x] = in[(size_t)(y + j) * C + x];
    __syncthreads();
    x = by + threadIdx.x;
    y = bx + threadIdx.y;
#pragma unroll
    for (int j = 0; j < 32; j += 8)
        if (y + j < C && x < R)
            out[(size_t)(y + j) * R + x] = __float2half_rn(t[threadIdx.x][threadIdx.y + j]);
}

__global__ void conv_h(const float* __restrict__ in, __half* __restrict__ out, long n4)
{
    long i = blockIdx.x * (long)blockDim.x + threadIdx.x;
    long stride = (long)gridDim.x * blockDim.x;
    for (; i < n4; i += stride) {
        float4 v = ((const float4*)in)[i];
        ((__half2*)out)[2 * i]     = __floats2half2_rn(v.x, v.y);
        ((__half2*)out)[2 * i + 1] = __floats2half2_rn(v.z, v.w);
    }
}

__global__ void spmm_h(const int* __restrict__ erow, const int* __restrict__ ecol,
                       const float* __restrict__ eval, const __half* __restrict__ x,
                       float* __restrict__ out, int nEdges, int d)
{
    int gw = (blockIdx.x * blockDim.x + threadIdx.x) >> 5;
    if (gw >= nEdges) return;
    int lane = threadIdx.x & 31;
    int r = erow[gw];
    int c = ecol[gw];
    float v = eval[gw];
    int off = blockIdx.y * 128 + lane * 4;
    const __half2* xp = (const __half2*)(x + (size_t)c * d + off);
    float2 f0 = __half22float2(xp[0]);
    float2 f1 = __half22float2(xp[1]);
    float4 add = make_float4(v * f0.x, v * f0.y, v * f1.x, v * f1.y);
    atomicAdd((float4*)(out + (size_t)r * d + off), add);
}

__global__ void zero_kernel(float4* __restrict__ p, long n4)
{
    long i = blockIdx.x * (long)blockDim.x + threadIdx.x;
    long stride = (long)gridDim.x * blockDim.x;
    for (; i < n4; i += stride) p[i] = make_float4(0.f, 0.f, 0.f, 0.f);
}

// hstr = relu(s2 + gc2_b) (fp32) and half copy into cat[:, 512:1024]
__global__ void bias_relu_out(const float* __restrict__ in, const float* __restrict__ b,
                              float* __restrict__ outF, __half* __restrict__ outH,
                              long total4, int d4)
{
    long i = blockIdx.x * (long)blockDim.x + threadIdx.x;
    long stride = (long)gridDim.x * blockDim.x;
    for (; i < total4; i += stride) {
        int  c4  = (int)(i % d4);
        long row = i / d4;
        float4 x  = ((const float4*)in)[i];
        float4 bb = ((const float4*)b)[c4];
        float4 y;
        y.x = fmaxf(x.x + bb.x, 0.f);
        y.y = fmaxf(x.y + bb.y, 0.f);
        y.z = fmaxf(x.z + bb.z, 0.f);
        y.w = fmaxf(x.w + bb.w, 0.f);
        ((float4*)outF)[i] = y;
        __half2* hp = (__half2*)(outH + row * 1024 + 512 + c4 * 4);
        hp[0] = __floats2half2_rn(y.x, y.y);
        hp[1] = __floats2half2_rn(y.z, y.w);
    }
}

// ---------------------------------------------------------------------------
extern "C" void kernel_launch(void* const* d_in, const int* in_sizes, int n_in,
                              void* d_out, int out_size)
{
    const float* seq    = (const float*)d_in[0];
    const float* go     = (const float*)d_in[1];
    const int*   erow   = (const int*)  d_in[2];
    const int*   ecol   = (const int*)  d_in[3];
    const float* eval_  = (const float*)d_in[4];
    const float* mlp_w1 = (const float*)d_in[5];
    const float* mlp_b1 = (const float*)d_in[6];
    const float* mlp_w2 = (const float*)d_in[7];
    const float* mlp_b2 = (const float*)d_in[8];
    const float* gc1_w  = (const float*)d_in[9];
    const float* gc1_b  = (const float*)d_in[10];
    const float* gc2_w  = (const float*)d_in[11];
    const float* gc2_b  = (const float*)d_in[12];
    const float* se_w1  = (const float*)d_in[13];
    const float* se_b1  = (const float*)d_in[14];
    const float* se_w2  = (const float*)d_in[15];
    const float* se_b2  = (const float*)d_in[16];

    float* out  = (float*)d_out;
    float* hsem = out;
    float* hstr = out + (size_t)N_GO * NHID1;
    float* pred = out + (size_t)2 * N_GO * NHID1;

    __half *goh, *seqh, *t1h, *xh, *g2h, *uh, *soh, *cath, *sp1h, *wth;
    float *s1, *s2;
    cudaGetSymbolAddress((void**)&goh,  g_goh);
    cudaGetSymbolAddress((void**)&seqh, g_seqh);
    cudaGetSymbolAddress((void**)&t1h,  g_t1h);
    cudaGetSymbolAddress((void**)&xh,   g_xh);
    cudaGetSymbolAddress((void**)&g2h,  g_g2h);
    cudaGetSymbolAddress((void**)&uh,   g_uh);
    cudaGetSymbolAddress((void**)&soh,  g_soh);
    cudaGetSymbolAddress((void**)&cath, g_cath);
    cudaGetSymbolAddress((void**)&sp1h, g_sp1h);
    cudaGetSymbolAddress((void**)&s1,   g_s1);
    cudaGetSymbolAddress((void**)&s2,   g_s2);
    cudaGetSymbolAddress((void**)&wth,  g_wth);

    __half* wt_mlp1 = wth + 0;
    __half* wt_mlp2 = wth + 524288;
    __half* wt_gc1  = wth + 1048576;
    __half* wt_gc2  = wth + 1572864;
    __half* wt_se1  = wth + 2097152;
    __half* wt_se2  = wth + 3407872;

    cudaFuncSetAttribute(gemm_h, cudaFuncAttributeMaxDynamicSharedMemorySize,
                         GEMM_SMEM_BYTES);

    // one-time host objects (no device memory involved)
    static cudaStream_t sB = nullptr;
    static cudaEvent_t evFork = nullptr, evJoin = nullptr;
    if (sB == nullptr) {
        cudaStreamCreateWithFlags(&sB, cudaStreamNonBlocking);
        cudaEventCreateWithFlags(&evFork, cudaEventDisableTiming);
        cudaEventCreateWithFlags(&evJoin, cudaEventDisableTiming);
    }

    const int T = 256;
    dim3 tb(32, 8);

    // ---- preamble (default stream): conversions, transposes, zeroing ----
    conv_h<<<2048, T>>>(go,  goh,  (long)N_GO * GO_FEAT / 4);
    conv_h<<<2048, T>>>(seq, seqh, (long)SEQ_B * SEQ_FEAT / 4);
    transpose_h<<<dim3(1024 / 32, 512 / 32),  tb>>>(mlp_w1, wt_mlp1, 512, 1024);
    transpose_h<<<dim3(512 / 32,  1024 / 32), tb>>>(mlp_w2, wt_mlp2, 1024, 512);
    transpose_h<<<dim3(1024 / 32, 512 / 32),  tb>>>(gc1_w,  wt_gc1,  512, 1024);
    transpose_h<<<dim3(512 / 32,  1024 / 32), tb>>>(gc2_w,  wt_gc2,  1024, 512);
    transpose_h<<<dim3(1024 / 32, 1280 / 32), tb>>>(se_w1,  wt_se1,  1280, 1024);
    transpose_h<<<dim3(1024 / 32, 1024 / 32), tb>>>(se_w2,  wt_se2,  1024, 1024);
    zero_kernel<<<2048, T>>>((float4*)s1, (long)N_GO * NHID1 / 4);
    zero_kernel<<<2048, T>>>((float4*)s2, (long)N_GO * NHID1 / 4);

    // ---- fork: side stream runs semantic + sequence GEMMs ----
    cudaEventRecord(evFork, 0);
    cudaStreamWaitEvent(sB, evFork, 0);

    const int MT_GO  = cdiv(N_GO, 128);   // 313
    const int MT_SEQ = SEQ_B / 128;       // 32

    // side stream B: semantic branch + sequence encoder (tensor-bound)
    gemm_h<<<dim3(NHID0 / 128, MT_GO), GEMM_T, GEMM_SMEM_BYTES, sB>>>(
        goh, wt_mlp1, mlp_b1, t1h, 1, nullptr, 0, N_GO, NHID0, GO_FEAT, 1, 0);
    gemm_h<<<dim3(NHID1 / 128, MT_GO), GEMM_T, GEMM_SMEM_BYTES, sB>>>(
        t1h, wt_mlp2, mlp_b2, hsem, 0, cath, 1024, N_GO, NHID1, NHID0, 0, 0);
    gemm_h<<<dim3(NHID0 / 128, MT_SEQ), GEMM_T, GEMM_SMEM_BYTES, sB>>>(
        seqh, wt_se1, se_b1, uh, 1, nullptr, 0, SEQ_B, NHID0, SEQ_FEAT, 1, 0);
    gemm_h<<<dim3(NHID0 / 128, MT_SEQ), GEMM_T, GEMM_SMEM_BYTES, sB>>>(
        uh, wt_se2, se_b2, soh, 1, nullptr, 0, SEQ_B, NHID0, NHID0, 0, 0);
    cudaEventRecord(evJoin, sB);

    // default stream: structure chain (spmm-heavy)
    spmm_h<<<dim3(N_EDGES * 32 / T, GO_FEAT / 128), T>>>(
        erow, ecol, eval_, goh, s1, N_EDGES, GO_FEAT);
    conv_h<<<2048, T>>>(s1, sp1h, (long)N_GO * NHID1 / 4);
    gemm_h<<<dim3(NHID0 / 128, MT_GO), GEMM_T, GEMM_SMEM_BYTES>>>(
        sp1h, wt_gc1, gc1_b, xh, 1, nullptr, 0, N_GO, NHID0, GO_FEAT, 1, 0);
    gemm_h<<<dim3(NHID1 / 128, MT_GO), GEMM_T, GEMM_SMEM_BYTES>>>(
        xh, wt_gc2, nullptr, g2h, 1, nullptr, 0, N_GO, NHID1, NHID0, 0, 0);
    spmm_h<<<dim3(N_EDGES * 32 / T, NHID1 / 128), T>>>(
        erow, ecol, eval_, g2h, s2, N_EDGES, NHID1);
    bias_relu_out<<<2048, T>>>(s2, gc2_b, hstr, cath,
                               (long)N_GO * NHID1 / 4, NHID1 / 4);

    // ---- join, then prediction GEMM ----
    cudaStreamWaitEvent(0, evJoin, 0);
    gemm_h<<<dim3(MT_SEQ, MT_GO), GEMM_T, GEMM_SMEM_BYTES>>>(
        soh, cath, nullptr, pred, 0, nullptr, 0, SEQ_B, N_GO, NHID0, 2, 1);
}